// round 2
// baseline (speedup 1.0000x reference)
#include <cuda_runtime.h>

#define NN 50000
#define EE 800000
#define E2 850000      // EE + NN self loops
#define HC 256
#define HEADS 4
#define HID 64
#define OUTD 86

// ---- scratch (device globals: allocation-free) ----
__device__ float g_h[NN * HC];          // post-GEMM features [N, H, C]
__device__ float g_agg[NN * HC];        // aggregation target / layer input
__device__ float g_as[NN * HEADS];
__device__ float g_ad[NN * HEADS];
__device__ float g_sum[NN * HEADS];     // softmax denominators
__device__ float g_ealpha[E2 * HEADS];  // exp(logit) per edge/head
__device__ float g_y[NN * HID];         // layer-2 head-mean output
__device__ float g_stats[2 * HC];       // BN sum / sumsq
__device__ int   g_src[E2];
__device__ int   g_dst[E2];
__device__ int   g_is64;

// ---------------- dtype probe: int64 edge_index has zero high words ----------------
__global__ void detect_dtype(const int* __restrict__ ei32) {
    if (blockIdx.x == 0 && threadIdx.x == 0) {
        int is64 = 1;
        for (int i = 0; i < 256; i++)
            if (ei32[2 * i + 1] != 0) { is64 = 0; break; }
        g_is64 = is64;
    }
}

// ---------------- normalize edge index to int32 + append self loops ----------------
__global__ void convert_idx(const void* __restrict__ eiv) {
    int e = blockIdx.x * blockDim.x + threadIdx.x;
    if (e >= E2) return;
    if (e >= EE) { g_src[e] = g_dst[e] = e - EE; return; }
    if (g_is64) {
        const long long* p = (const long long*)eiv;
        g_src[e] = (int)p[e];
        g_dst[e] = (int)p[EE + e];
    } else {
        const int* p = (const int*)eiv;
        g_src[e] = p[e];
        g_dst[e] = p[EE + e];
    }
}

// ---------------- SGEMM: C[M,Nc] = A[M,K] @ B[K,Nc]  (Nc % 64 == 0) ----------------
__global__ void sgemm64(const float* __restrict__ A, const float* __restrict__ B,
                        float* __restrict__ C, int M, int Nc, int K) {
    __shared__ float As[16][65];
    __shared__ float Bs[16][64];
    int tid = threadIdx.x;
    int tx = tid & 15, ty = tid >> 4;
    int rowBase = blockIdx.y * 64, colBase = blockIdx.x * 64;
    float acc[4][4] = {};
    for (int k0 = 0; k0 < K; k0 += 16) {
        #pragma unroll
        for (int l = tid; l < 1024; l += 256) {
            int r = l >> 4, c = l & 15;
            int gr = rowBase + r;
            As[c][r] = (gr < M) ? A[(long)gr * K + k0 + c] : 0.f;
        }
        #pragma unroll
        for (int l = tid; l < 1024; l += 256) {
            int r = l >> 6, c = l & 63;
            Bs[r][c] = B[(long)(k0 + r) * Nc + colBase + c];
        }
        __syncthreads();
        #pragma unroll
        for (int k = 0; k < 16; k++) {
            float a[4], b[4];
            #pragma unroll
            for (int i = 0; i < 4; i++) a[i] = As[k][ty + i * 16];
            #pragma unroll
            for (int j = 0; j < 4; j++) b[j] = Bs[k][tx + j * 16];
            #pragma unroll
            for (int i = 0; i < 4; i++)
                #pragma unroll
                for (int j = 0; j < 4; j++)
                    acc[i][j] += a[i] * b[j];
        }
        __syncthreads();
    }
    #pragma unroll
    for (int i = 0; i < 4; i++) {
        int gr = rowBase + ty + i * 16;
        if (gr < M) {
            #pragma unroll
            for (int j = 0; j < 4; j++)
                C[(long)gr * Nc + colBase + tx + j * 16] = acc[i][j];
        }
    }
}

// ---------------- attention scores: a_s[n,h] = <h[n,h,:], att_s[h,:]> ----------------
__global__ void attn_scores(const float* __restrict__ attS, const float* __restrict__ attD) {
    int idx = blockIdx.x * blockDim.x + threadIdx.x;
    if (idx >= NN * HEADS) return;
    int n = idx >> 2, hh = idx & 3;
    const float* hp = g_h + (long)n * HC + hh * HID;
    const float* as = attS + hh * HID;
    const float* ad = attD + hh * HID;
    float ss = 0.f, sd = 0.f;
    #pragma unroll
    for (int k = 0; k < HID; k++) {
        float v = hp[k];
        ss += v * as[k];
        sd += v * ad[k];
    }
    g_as[idx] = ss;
    g_ad[idx] = sd;
}

// ---------------- zero scratch before an edge pass ----------------
__global__ void zero_pre() {
    int i = blockIdx.x * blockDim.x + threadIdx.x;
    int stride = gridDim.x * blockDim.x;
    for (int j = i; j < NN * HC; j += stride) g_agg[j] = 0.f;
    for (int j = i; j < NN * HEADS; j += stride) g_sum[j] = 0.f;
    if (i < 2 * HC) g_stats[i] = 0.f;
}

// ---------------- edge pass 1: exp(leaky(logit)) + denominator (v4 red) ----------------
__global__ void edge_soft() {
    int e = blockIdx.x * blockDim.x + threadIdx.x;
    if (e >= E2) return;
    int s = g_src[e], d = g_dst[e];
    float4 sv = *(const float4*)(g_as + s * HEADS);
    float4 dv = *(const float4*)(g_ad + d * HEADS);
    float4 ex;
    float l0 = sv.x + dv.x; l0 = fmaxf(l0, 0.2f * l0); ex.x = __expf(l0);
    float l1 = sv.y + dv.y; l1 = fmaxf(l1, 0.2f * l1); ex.y = __expf(l1);
    float l2 = sv.z + dv.z; l2 = fmaxf(l2, 0.2f * l2); ex.z = __expf(l2);
    float l3 = sv.w + dv.w; l3 = fmaxf(l3, 0.2f * l3); ex.w = __expf(l3);
    *(float4*)(g_ealpha + e * HEADS) = ex;
    float* dstp = g_sum + d * HEADS;
    asm volatile("red.global.add.v4.f32 [%0], {%1, %2, %3, %4};"
                 :: "l"(dstp), "f"(ex.x), "f"(ex.y), "f"(ex.z), "f"(ex.w) : "memory");
}

// ---------------- edge pass 2: agg[dst] += alpha * h[src]  (warp per edge, v4 red) ----------------
__global__ void edge_agg() {
    int widx = (blockIdx.x * blockDim.x + threadIdx.x) >> 5;
    int lane = threadIdx.x & 31;
    if (widx >= E2) return;
    int s = g_src[widx], d = g_dst[widx];
    int hh = lane >> 3;                       // 8 lanes per head, 8 floats per lane
    float al = g_ealpha[widx * HEADS + hh] / (g_sum[d * HEADS + hh] + 1e-16f);
    const float4* hs4 = (const float4*)(g_h + (long)s * HC) + lane * 2;
    float* ag = g_agg + (long)d * HC + lane * 8;
    float4 v0 = hs4[0], v1 = hs4[1];
    v0.x *= al; v0.y *= al; v0.z *= al; v0.w *= al;
    v1.x *= al; v1.y *= al; v1.z *= al; v1.w *= al;
    asm volatile("red.global.add.v4.f32 [%0], {%1, %2, %3, %4};"
                 :: "l"(ag), "f"(v0.x), "f"(v0.y), "f"(v0.z), "f"(v0.w) : "memory");
    asm volatile("red.global.add.v4.f32 [%0], {%1, %2, %3, %4};"
                 :: "l"(ag + 4), "f"(v1.x), "f"(v1.y), "f"(v1.z), "f"(v1.w) : "memory");
}

// ---------------- BN stats: per-channel sum & sumsq ----------------
__global__ void bn_stats(const float* __restrict__ x, const float* __restrict__ bias,
                         int N, int C) {
    int tid = threadIdx.x;
    int c = tid % C;
    int g = tid / C;
    int G = blockDim.x / C;
    int rows_per_block = (N + gridDim.x - 1) / gridDim.x;
    int r0 = blockIdx.x * rows_per_block;
    int r1 = min(N, r0 + rows_per_block);
    float b = bias ? bias[c] : 0.f;
    float s = 0.f, q = 0.f;
    for (int r = r0 + g; r < r1; r += G) {
        float v = x[(long)r * C + c] + b;
        s += v;
        q += v * v;
    }
    __shared__ float sh[512];
    sh[tid] = s;
    sh[256 + tid] = q;
    __syncthreads();
    if (g == 0) {
        for (int gg = 1; gg < G; gg++) {
            s += sh[gg * C + c];
            q += sh[256 + gg * C + c];
        }
        atomicAdd(&g_stats[c], s);
        atomicAdd(&g_stats[C + c], q);
    }
}

// ---------------- BN apply + activation (act 0 = PReLU, 1 = ELU) ----------------
__global__ void bn_apply(float* __restrict__ x, const float* __restrict__ bias,
                         const float* __restrict__ gamma, const float* __restrict__ beta,
                         int N, int C, int act, const float* __restrict__ pw) {
    int i = blockIdx.x * blockDim.x + threadIdx.x;
    if (i >= N * C) return;
    int c = i % C;
    float invN = 1.f / (float)N;
    float mean = g_stats[c] * invN;
    float var = g_stats[C + c] * invN - mean * mean;
    float inv = rsqrtf(var + 1e-5f);
    float v = x[i] + (bias ? bias[c] : 0.f);
    v = (v - mean) * inv * gamma[c] + beta[c];
    if (act == 0) {
        float w = pw[0];
        v = (v >= 0.f) ? v : w * v;
    } else {
        v = (v > 0.f) ? v : expm1f(v);
    }
    x[i] = v;
}

// ---------------- layer-2 head mean + bias ----------------
__global__ void head_mean(const float* __restrict__ b2) {
    int i = blockIdx.x * blockDim.x + threadIdx.x;
    if (i >= NN * HID) return;
    int n = i >> 6, c = i & 63;
    const float* a = g_agg + (long)n * HC;
    g_y[i] = 0.25f * (a[c] + a[64 + c] + a[128 + c] + a[192 + c]) + b2[c];
}

// ---------------- final linear [N,64] @ [64,86] + b ----------------
__global__ void fc_out(const float* __restrict__ W, const float* __restrict__ b,
                       float* __restrict__ out) {
    int i = blockIdx.x * blockDim.x + threadIdx.x;
    if (i >= NN * OUTD) return;
    int n = i / OUTD, o = i - n * OUTD;
    const float* y = g_y + (long)n * HID;
    float acc = b[o];
    #pragma unroll
    for (int k = 0; k < HID; k++) acc += y[k] * W[k * OUTD + o];
    out[i] = acc;
}

extern "C" void kernel_launch(void* const* d_in, const int* in_sizes, int n_in,
                              void* d_out, int out_size) {
    const float* x   = (const float*)d_in[0];
    const void*  ei  = d_in[1];
    const float* W1  = (const float*)d_in[2];
    const float* as1 = (const float*)d_in[3];
    const float* ad1 = (const float*)d_in[4];
    const float* b1  = (const float*)d_in[5];
    const float* W2  = (const float*)d_in[6];
    const float* as2 = (const float*)d_in[7];
    const float* ad2 = (const float*)d_in[8];
    const float* b2  = (const float*)d_in[9];
    const float* g1  = (const float*)d_in[10];
    const float* be1 = (const float*)d_in[11];
    const float* g2  = (const float*)d_in[12];
    const float* be2 = (const float*)d_in[13];
    const float* pw  = (const float*)d_in[14];
    const float* fcW = (const float*)d_in[15];
    const float* fcb = (const float*)d_in[16];
    float* out = (float*)d_out;

    float *p_h, *p_agg, *p_y;
    cudaGetSymbolAddress((void**)&p_h, g_h);
    cudaGetSymbolAddress((void**)&p_agg, g_agg);
    cudaGetSymbolAddress((void**)&p_y, g_y);

    dim3 gemmGrid(HC / 64, (NN + 63) / 64);
    int attnBlocks = (NN * HEADS + 255) / 256;
    int softBlocks = (E2 + 255) / 256;
    int aggBlocks  = (E2 * 32 + 255) / 256;

    detect_dtype<<<1, 32>>>((const int*)ei);
    convert_idx<<<(E2 + 255) / 256, 256>>>(ei);

    // ---- layer 1 ----
    sgemm64<<<gemmGrid, 256>>>(x, W1, p_h, NN, HC, 256);
    attn_scores<<<attnBlocks, 256>>>(as1, ad1);
    zero_pre<<<2048, 256>>>();
    edge_soft<<<softBlocks, 256>>>();
    edge_agg<<<aggBlocks, 256>>>();
    bn_stats<<<128, 256>>>(p_agg, b1, NN, HC);
    bn_apply<<<(NN * HC + 255) / 256, 256>>>(p_agg, b1, g1, be1, NN, HC, 0, pw);

    // ---- layer 2 ----
    sgemm64<<<gemmGrid, 256>>>(p_agg, W2, p_h, NN, HC, HC);
    attn_scores<<<attnBlocks, 256>>>(as2, ad2);
    zero_pre<<<2048, 256>>>();
    edge_soft<<<softBlocks, 256>>>();
    edge_agg<<<aggBlocks, 256>>>();
    head_mean<<<(NN * HID + 255) / 256, 256>>>(b2);
    bn_stats<<<128, 256>>>(p_y, nullptr, NN, HID);
    bn_apply<<<(NN * HID + 255) / 256, 256>>>(p_y, nullptr, g2, be2, NN, HID, 1, pw);
    fc_out<<<(NN * OUTD + 255) / 256, 256>>>(fcW, fcb, out);
}

// round 3
// speedup vs baseline: 1.6366x; 1.6366x over previous
#include <cuda_runtime.h>

#define NN 50000
#define EE 800000
#define E2 850000      // EE + NN self loops
#define HC 256
#define HEADS 4
#define HID 64
#define OUTD 86
#define SCAN_BLK 256
#define NBLK_SCAN ((NN + SCAN_BLK - 1) / SCAN_BLK)   // 196

// ---- scratch (device globals: allocation-free) ----
__device__ float g_h[NN * HC];          // post-GEMM features [N, H, C]
__device__ float g_agg[NN * HC];        // aggregation output / layer input
__device__ float g_as[NN * HEADS];
__device__ float g_ad[NN * HEADS];
__device__ float g_ealpha[E2 * HEADS];  // exp(logit) per csr-pos/head
__device__ float g_y[NN * HID];         // layer-2 head-mean output
__device__ float g_stats[2 * HC];       // BN sum / sumsq
__device__ int   g_src[E2];
__device__ int   g_dst[E2];
__device__ int   g_rank[E2];
__device__ int   g_deg[NN];
__device__ int   g_off[NN + 1];
__device__ int   g_bsum[SCAN_BLK];
__device__ int   g_boff[SCAN_BLK];
__device__ int   g_csr[E2];             // src node per csr position
__device__ int   g_is64;

// ---------------- dtype probe: int64 edge_index has zero high words ----------------
__global__ void detect_dtype(const int* __restrict__ ei32) {
    if (threadIdx.x == 0) {
        int is64 = 1;
        for (int i = 0; i < 256; i++)
            if (ei32[2 * i + 1] != 0) { is64 = 0; break; }
        g_is64 = is64;
    }
}

// ---------------- normalize edge index + self loops; zero deg ----------------
__global__ void convert_idx(const void* __restrict__ eiv) {
    int e = blockIdx.x * blockDim.x + threadIdx.x;
    if (e < NN) g_deg[e] = 0;
    if (e >= E2) return;
    if (e >= EE) { g_src[e] = g_dst[e] = e - EE; return; }
    if (g_is64) {
        const long long* p = (const long long*)eiv;
        g_src[e] = (int)p[e];
        g_dst[e] = (int)p[EE + e];
    } else {
        const int* p = (const int*)eiv;
        g_src[e] = p[e];
        g_dst[e] = p[EE + e];
    }
}

// ---------------- degree histogram + per-edge rank ----------------
__global__ void hist_deg() {
    int e = blockIdx.x * blockDim.x + threadIdx.x;
    if (e >= E2) return;
    g_rank[e] = atomicAdd(&g_deg[g_dst[e]], 1);
}

// ---------------- scan stage 1: per-block sums ----------------
__global__ void scan1() {
    __shared__ int sh[SCAN_BLK];
    int t = threadIdx.x, b = blockIdx.x;
    int idx = b * SCAN_BLK + t;
    sh[t] = (idx < NN) ? g_deg[idx] : 0;
    __syncthreads();
    for (int o = 128; o > 0; o >>= 1) {
        if (t < o) sh[t] += sh[t + o];
        __syncthreads();
    }
    if (t == 0) g_bsum[b] = sh[0];
}

// ---------------- scan stage 2: exclusive scan of block sums ----------------
__global__ void scan2() {
    __shared__ int sh[SCAN_BLK];
    int t = threadIdx.x;
    sh[t] = (t < NBLK_SCAN) ? g_bsum[t] : 0;
    __syncthreads();
    int v = sh[t];
    for (int o = 1; o < SCAN_BLK; o <<= 1) {
        int u = (t >= o) ? sh[t - o] : 0;
        __syncthreads();
        sh[t] += u;
        __syncthreads();
    }
    g_boff[t] = sh[t] - v;          // exclusive
    if (t == 0) g_off[NN] = E2;
}

// ---------------- scan stage 3: per-block exclusive scan + offset ----------------
__global__ void scan3() {
    __shared__ int sh[SCAN_BLK];
    int t = threadIdx.x, b = blockIdx.x;
    int idx = b * SCAN_BLK + t;
    int v = (idx < NN) ? g_deg[idx] : 0;
    sh[t] = v;
    __syncthreads();
    for (int o = 1; o < SCAN_BLK; o <<= 1) {
        int u = (t >= o) ? sh[t - o] : 0;
        __syncthreads();
        sh[t] += u;
        __syncthreads();
    }
    if (idx < NN) g_off[idx] = g_boff[b] + sh[t] - v;
}

// ---------------- scatter into CSR ----------------
__global__ void scatter_csr() {
    int e = blockIdx.x * blockDim.x + threadIdx.x;
    if (e >= E2) return;
    g_csr[g_off[g_dst[e]] + g_rank[e]] = g_src[e];
}

// ---------------- GEMM 128x64 tile + fused attention scores ----------------
// C[M,Nc] = A[M,K] @ B[K,Nc]; col-tile == one head; writes g_as/g_ad.
__global__ void gemm_fused(const float* __restrict__ A, const float* __restrict__ B,
                           float* __restrict__ C, const float* __restrict__ attS,
                           const float* __restrict__ attD, int M, int Nc, int K) {
    __shared__ float As[16][129];
    __shared__ float Bs[16][64];
    int tid = threadIdx.x;
    int tx = tid & 15, ty = tid >> 4;
    int rowBase = blockIdx.y * 128, colBase = blockIdx.x * 64;
    int hh = blockIdx.x;
    float aS[4], aD[4];
    #pragma unroll
    for (int j = 0; j < 4; j++) {
        aS[j] = attS[hh * HID + tx + j * 16];
        aD[j] = attD[hh * HID + tx + j * 16];
    }
    float acc[8][4] = {};
    for (int k0 = 0; k0 < K; k0 += 16) {
        #pragma unroll
        for (int it = 0; it < 8; it++) {
            int l = tid + it * 256;
            int r = l >> 4, c = l & 15;
            int gr = rowBase + r;
            As[c][r] = (gr < M) ? A[(long)gr * K + k0 + c] : 0.f;
        }
        #pragma unroll
        for (int it = 0; it < 4; it++) {
            int l = tid + it * 256;
            int r = l >> 6, c = l & 63;
            Bs[r][c] = B[(long)(k0 + r) * Nc + colBase + c];
        }
        __syncthreads();
        #pragma unroll
        for (int k = 0; k < 16; k++) {
            float a[8], b[4];
            #pragma unroll
            for (int i = 0; i < 8; i++) a[i] = As[k][ty + i * 16];
            #pragma unroll
            for (int j = 0; j < 4; j++) b[j] = Bs[k][tx + j * 16];
            #pragma unroll
            for (int i = 0; i < 8; i++)
                #pragma unroll
                for (int j = 0; j < 4; j++)
                    acc[i][j] += a[i] * b[j];
        }
        __syncthreads();
    }
    #pragma unroll
    for (int i = 0; i < 8; i++) {
        int gr = rowBase + ty + i * 16;
        float ss = 0.f, sd = 0.f;
        #pragma unroll
        for (int j = 0; j < 4; j++) {
            ss += acc[i][j] * aS[j];
            sd += acc[i][j] * aD[j];
        }
        #pragma unroll
        for (int o = 8; o > 0; o >>= 1) {
            ss += __shfl_xor_sync(0xffffffffu, ss, o);
            sd += __shfl_xor_sync(0xffffffffu, sd, o);
        }
        if (gr < M) {
            #pragma unroll
            for (int j = 0; j < 4; j++)
                C[(long)gr * Nc + colBase + tx + j * 16] = acc[i][j];
            if (tx == 0) {
                g_as[gr * HEADS + hh] = ss;
                g_ad[gr * HEADS + hh] = sd;
            }
        }
    }
}

// ---------------- CSR aggregation: warp per dst node, no atomics ----------------
__global__ void agg_csr(const float* __restrict__ hsrc, float* __restrict__ outp) {
    int d = (blockIdx.x * blockDim.x + threadIdx.x) >> 5;
    int lane = threadIdx.x & 31;
    if (d >= NN) return;
    int start = g_off[d], end = g_off[d + 1];
    float4 dv = *(const float4*)(g_ad + d * HEADS);
    float d0 = 0.f, d1 = 0.f, d2 = 0.f, d3 = 0.f;
    for (int e = start + lane; e < end; e += 32) {
        int s = g_csr[e];
        float4 sv = *(const float4*)(g_as + s * HEADS);
        float4 ex;
        float l0 = sv.x + dv.x; l0 = fmaxf(l0, 0.2f * l0); ex.x = __expf(l0);
        float l1 = sv.y + dv.y; l1 = fmaxf(l1, 0.2f * l1); ex.y = __expf(l1);
        float l2 = sv.z + dv.z; l2 = fmaxf(l2, 0.2f * l2); ex.z = __expf(l2);
        float l3 = sv.w + dv.w; l3 = fmaxf(l3, 0.2f * l3); ex.w = __expf(l3);
        *(float4*)(g_ealpha + (long)e * HEADS) = ex;
        d0 += ex.x; d1 += ex.y; d2 += ex.z; d3 += ex.w;
    }
    #pragma unroll
    for (int o = 16; o > 0; o >>= 1) {
        d0 += __shfl_xor_sync(0xffffffffu, d0, o);
        d1 += __shfl_xor_sync(0xffffffffu, d1, o);
        d2 += __shfl_xor_sync(0xffffffffu, d2, o);
        d3 += __shfl_xor_sync(0xffffffffu, d3, o);
    }
    int hh = lane >> 3;
    float den = (hh == 0) ? d0 : (hh == 1) ? d1 : (hh == 2) ? d2 : d3;
    float invh = 1.f / (den + 1e-16f);
    float4 a0 = {0.f, 0.f, 0.f, 0.f}, a1 = {0.f, 0.f, 0.f, 0.f};
    for (int e = start; e < end; e++) {
        int s = g_csr[e];
        float al = g_ealpha[(long)e * HEADS + hh] * invh;
        const float4* hp = (const float4*)(hsrc + (long)s * HC) + lane * 2;
        float4 v0 = hp[0], v1 = hp[1];
        a0.x += al * v0.x; a0.y += al * v0.y; a0.z += al * v0.z; a0.w += al * v0.w;
        a1.x += al * v1.x; a1.y += al * v1.y; a1.z += al * v1.z; a1.w += al * v1.w;
    }
    float4* op = (float4*)(outp + (long)d * HC) + lane * 2;
    op[0] = a0;
    op[1] = a1;
}

// ---------------- zero BN stats ----------------
__global__ void zero_stats() {
    int i = threadIdx.x;
    g_stats[i] = 0.f;
    g_stats[i + 256] = 0.f;
}

// ---------------- BN stats: per-channel sum & sumsq ----------------
__global__ void bn_stats(const float* __restrict__ x, const float* __restrict__ bias,
                         int N, int C) {
    int tid = threadIdx.x;
    int c = tid % C;
    int g = tid / C;
    int G = blockDim.x / C;
    int rows_per_block = (N + gridDim.x - 1) / gridDim.x;
    int r0 = blockIdx.x * rows_per_block;
    int r1 = min(N, r0 + rows_per_block);
    float b = bias ? bias[c] : 0.f;
    float s = 0.f, q = 0.f;
    for (int r = r0 + g; r < r1; r += G) {
        float v = x[(long)r * C + c] + b;
        s += v;
        q += v * v;
    }
    __shared__ float sh[512];
    sh[tid] = s;
    sh[256 + tid] = q;
    __syncthreads();
    if (g == 0) {
        for (int gg = 1; gg < G; gg++) {
            s += sh[gg * C + c];
            q += sh[256 + gg * C + c];
        }
        atomicAdd(&g_stats[c], s);
        atomicAdd(&g_stats[C + c], q);
    }
}

// ---------------- BN apply + activation (act 0 = PReLU, 1 = ELU) ----------------
__global__ void bn_apply(float* __restrict__ x, const float* __restrict__ bias,
                         const float* __restrict__ gamma, const float* __restrict__ beta,
                         int N, int C, int act, const float* __restrict__ pw) {
    int i = blockIdx.x * blockDim.x + threadIdx.x;
    if (i >= N * C) return;
    int c = i % C;
    float invN = 1.f / (float)N;
    float mean = g_stats[c] * invN;
    float var = g_stats[C + c] * invN - mean * mean;
    float inv = rsqrtf(var + 1e-5f);
    float v = x[i] + (bias ? bias[c] : 0.f);
    v = (v - mean) * inv * gamma[c] + beta[c];
    if (act == 0) {
        float w = pw[0];
        v = (v >= 0.f) ? v : w * v;
    } else {
        v = (v > 0.f) ? v : expm1f(v);
    }
    x[i] = v;
}

// ---------------- layer-2 head mean + bias ----------------
__global__ void head_mean(const float* __restrict__ b2) {
    int i = blockIdx.x * blockDim.x + threadIdx.x;
    if (i >= NN * HID) return;
    int n = i >> 6, c = i & 63;
    const float* a = g_agg + (long)n * HC;
    g_y[i] = 0.25f * (a[c] + a[64 + c] + a[128 + c] + a[192 + c]) + b2[c];
}

// ---------------- final linear [N,64] @ [64,86] + b (W in smem) ----------------
__global__ void fc_out(const float* __restrict__ W, const float* __restrict__ b,
                       float* __restrict__ out) {
    __shared__ float sW[HID * OUTD];
    for (int l = threadIdx.x; l < HID * OUTD; l += blockDim.x)
        sW[l] = W[l];
    __syncthreads();
    int i = blockIdx.x * blockDim.x + threadIdx.x;
    if (i >= NN * OUTD) return;
    int n = i / OUTD, o = i - n * OUTD;
    const float* y = g_y + (long)n * HID;
    float acc = b[o];
    #pragma unroll
    for (int k = 0; k < HID; k++) acc += y[k] * sW[k * OUTD + o];
    out[i] = acc;
}

extern "C" void kernel_launch(void* const* d_in, const int* in_sizes, int n_in,
                              void* d_out, int out_size) {
    const float* x   = (const float*)d_in[0];
    const void*  ei  = d_in[1];
    const float* W1  = (const float*)d_in[2];
    const float* as1 = (const float*)d_in[3];
    const float* ad1 = (const float*)d_in[4];
    const float* b1  = (const float*)d_in[5];
    const float* W2  = (const float*)d_in[6];
    const float* as2 = (const float*)d_in[7];
    const float* ad2 = (const float*)d_in[8];
    const float* b2  = (const float*)d_in[9];
    const float* g1  = (const float*)d_in[10];
    const float* be1 = (const float*)d_in[11];
    const float* g2  = (const float*)d_in[12];
    const float* be2 = (const float*)d_in[13];
    const float* pw  = (const float*)d_in[14];
    const float* fcW = (const float*)d_in[15];
    const float* fcb = (const float*)d_in[16];
    float* out = (float*)d_out;

    float *p_h, *p_agg, *p_y;
    cudaGetSymbolAddress((void**)&p_h, g_h);
    cudaGetSymbolAddress((void**)&p_agg, g_agg);
    cudaGetSymbolAddress((void**)&p_y, g_y);

    dim3 gemmGrid(HC / 64, (NN + 127) / 128);
    int edgeBlocks = (E2 + 255) / 256;
    int aggBlocks  = (NN * 32 + 255) / 256;

    // ---- CSR build (once, reused by both layers) ----
    detect_dtype<<<1, 32>>>((const int*)ei);
    convert_idx<<<edgeBlocks, 256>>>(ei);
    hist_deg<<<edgeBlocks, 256>>>();
    scan1<<<NBLK_SCAN, SCAN_BLK>>>();
    scan2<<<1, SCAN_BLK>>>();
    scan3<<<NBLK_SCAN, SCAN_BLK>>>();
    scatter_csr<<<edgeBlocks, 256>>>();

    // ---- layer 1 ----
    gemm_fused<<<gemmGrid, 256>>>(x, W1, p_h, as1, ad1, NN, HC, 256);
    agg_csr<<<aggBlocks, 256>>>(p_h, p_agg);
    zero_stats<<<1, 256>>>();
    bn_stats<<<128, 256>>>(p_agg, b1, NN, HC);
    bn_apply<<<(NN * HC + 255) / 256, 256>>>(p_agg, b1, g1, be1, NN, HC, 0, pw);

    // ---- layer 2 ----
    gemm_fused<<<gemmGrid, 256>>>(p_agg, W2, p_h, as2, ad2, NN, HC, HC);
    agg_csr<<<aggBlocks, 256>>>(p_h, p_agg);
    head_mean<<<(NN * HID + 255) / 256, 256>>>(b2);
    zero_stats<<<1, 256>>>();
    bn_stats<<<128, 256>>>(p_y, nullptr, NN, HID);
    bn_apply<<<(NN * HID + 255) / 256, 256>>>(p_y, nullptr, g2, be2, NN, HID, 1, pw);
    fc_out<<<(NN * OUTD + 255) / 256, 256>>>(fcW, fcb, out);
}

// round 4
// speedup vs baseline: 2.6043x; 1.5913x over previous
#include <cuda_runtime.h>

#define NN 50000
#define EE 800000
#define E2 850000      // EE + NN self loops
#define HC 256
#define HEADS 4
#define HID 64
#define OUTD 86
#define SCAN_BLK 256
#define NBLK_SCAN ((NN + SCAN_BLK - 1) / SCAN_BLK)   // 196

// GEMM tiling
#define BM 128
#define BN 64
#define BK 32
#define ASTRIDE 36     // conflict-free A frag loads
#define BSTRIDE 72     // conflict-free B frag loads
#define ASZ (BM * ASTRIDE)
#define BSZ (BK * BSTRIDE)
#define GEMM_SMEM ((2 * ASZ + 2 * BSZ + 2 * BM * 2) * 4)

// ---- scratch (device globals: allocation-free) ----
__device__ float g_h[NN * HC];          // post-GEMM features [N, H, C]
__device__ float g_agg[NN * HC];        // aggregation output / layer input
__device__ float g_as[NN * HEADS];
__device__ float g_ad[NN * HEADS];
__device__ float g_ealpha[E2 * HEADS];  // exp(logit) per csr-pos/head
__device__ float g_y[NN * HID];         // layer-2 head-mean output
__device__ float g_stats[2 * HC];       // BN sum / sumsq
__device__ int   g_src[E2];
__device__ int   g_dst[E2];
__device__ int   g_rank[E2];
__device__ int   g_deg[NN];
__device__ int   g_off[NN + 1];
__device__ int   g_bsum[SCAN_BLK];
__device__ int   g_boff[SCAN_BLK];
__device__ int   g_csr[E2];             // src node per csr position
__device__ int   g_is64;

// ---------------- dtype probe: int64 edge_index has zero high words ----------------
__global__ void detect_dtype(const int* __restrict__ ei32) {
    if (threadIdx.x == 0) {
        int is64 = 1;
        for (int i = 0; i < 256; i++)
            if (ei32[2 * i + 1] != 0) { is64 = 0; break; }
        g_is64 = is64;
    }
}

// ---------------- normalize edge index + self loops; zero deg ----------------
__global__ void convert_idx(const void* __restrict__ eiv) {
    int e = blockIdx.x * blockDim.x + threadIdx.x;
    if (e < NN) g_deg[e] = 0;
    if (e >= E2) return;
    if (e >= EE) { g_src[e] = g_dst[e] = e - EE; return; }
    if (g_is64) {
        const long long* p = (const long long*)eiv;
        g_src[e] = (int)p[e];
        g_dst[e] = (int)p[EE + e];
    } else {
        const int* p = (const int*)eiv;
        g_src[e] = p[e];
        g_dst[e] = p[EE + e];
    }
}

// ---------------- degree histogram + per-edge rank ----------------
__global__ void hist_deg() {
    int e = blockIdx.x * blockDim.x + threadIdx.x;
    if (e >= E2) return;
    g_rank[e] = atomicAdd(&g_deg[g_dst[e]], 1);
}

// ---------------- scan stage 1: per-block sums ----------------
__global__ void scan1() {
    __shared__ int sh[SCAN_BLK];
    int t = threadIdx.x, b = blockIdx.x;
    int idx = b * SCAN_BLK + t;
    sh[t] = (idx < NN) ? g_deg[idx] : 0;
    __syncthreads();
    for (int o = 128; o > 0; o >>= 1) {
        if (t < o) sh[t] += sh[t + o];
        __syncthreads();
    }
    if (t == 0) g_bsum[b] = sh[0];
}

// ---------------- scan stage 2: exclusive scan of block sums ----------------
__global__ void scan2() {
    __shared__ int sh[SCAN_BLK];
    int t = threadIdx.x;
    sh[t] = (t < NBLK_SCAN) ? g_bsum[t] : 0;
    __syncthreads();
    int v = sh[t];
    for (int o = 1; o < SCAN_BLK; o <<= 1) {
        int u = (t >= o) ? sh[t - o] : 0;
        __syncthreads();
        sh[t] += u;
        __syncthreads();
    }
    g_boff[t] = sh[t] - v;          // exclusive
    if (t == 0) g_off[NN] = E2;
}

// ---------------- scan stage 3: per-block exclusive scan + offset ----------------
__global__ void scan3() {
    __shared__ int sh[SCAN_BLK];
    int t = threadIdx.x, b = blockIdx.x;
    int idx = b * SCAN_BLK + t;
    int v = (idx < NN) ? g_deg[idx] : 0;
    sh[t] = v;
    __syncthreads();
    for (int o = 1; o < SCAN_BLK; o <<= 1) {
        int u = (t >= o) ? sh[t - o] : 0;
        __syncthreads();
        sh[t] += u;
        __syncthreads();
    }
    if (idx < NN) g_off[idx] = g_boff[b] + sh[t] - v;
}

// ---------------- scatter into CSR ----------------
__global__ void scatter_csr() {
    int e = blockIdx.x * blockDim.x + threadIdx.x;
    if (e >= E2) return;
    g_csr[g_off[g_dst[e]] + g_rank[e]] = g_src[e];
}

// ---------------- TF32 tensor-core GEMM + fused attention scores ----------------
__device__ __forceinline__ unsigned f2tf(float x) {
    unsigned r;
    asm("cvt.rna.tf32.f32 %0, %1;" : "=r"(r) : "f"(x));
    return r;
}

__global__ __launch_bounds__(256) void gemm_tf32(
        const float* __restrict__ A, const float* __restrict__ B,
        float* __restrict__ C, const float* __restrict__ attS,
        const float* __restrict__ attD, int M) {
    extern __shared__ float sm[];
    float* sA = sm;                      // [2][ASZ]
    float* sB = sm + 2 * ASZ;            // [2][BSZ]
    float* sRed = sm + 2 * ASZ + 2 * BSZ;// [2][BM][2]
    const int K = 256;
    int tid = threadIdx.x, lane = tid & 31, warp = tid >> 5;
    int wm = warp >> 1, wn = warp & 1;   // 4x2 warp grid, 32x32 per warp
    int g = lane >> 2, tg = lane & 3;
    int rowBase = blockIdx.y * BM;
    int hh = blockIdx.x;

    float acc[2][4][4];
    #pragma unroll
    for (int mt = 0; mt < 2; mt++)
        #pragma unroll
        for (int nt = 0; nt < 4; nt++)
            #pragma unroll
            for (int i = 0; i < 4; i++) acc[mt][nt][i] = 0.f;

    // global-load register staging
    float4 av[4], bv[2];
    // A: 4 float4 per thread. F = tid + i*256 : row=F>>3, col=(F&7)*4
    // B: 2 float4 per thread. F = tid + i*256 : row=F>>4, col=(F&15)*4
    auto loadA = [&](int k0) {
        #pragma unroll
        for (int i = 0; i < 4; i++) {
            int F = tid + i * 256;
            int r = rowBase + (F >> 3);
            int c = (F & 7) * 4;
            av[i] = (r < M) ? *(const float4*)(A + (long)r * K + k0 + c)
                            : make_float4(0.f, 0.f, 0.f, 0.f);
        }
        #pragma unroll
        for (int i = 0; i < 2; i++) {
            int F = tid + i * 256;
            int r = k0 + (F >> 4);
            int c = hh * BN + (F & 15) * 4;
            bv[i] = *(const float4*)(B + (long)r * HC + c);
        }
    };
    auto storeT = [&](int buf) {
        float* pA = sA + buf * ASZ;
        #pragma unroll
        for (int i = 0; i < 4; i++) {
            int F = tid + i * 256;
            int r = F >> 3, c = (F & 7) * 4;
            float4 v;
            v.x = __uint_as_float(f2tf(av[i].x));
            v.y = __uint_as_float(f2tf(av[i].y));
            v.z = __uint_as_float(f2tf(av[i].z));
            v.w = __uint_as_float(f2tf(av[i].w));
            *(float4*)(pA + r * ASTRIDE + c) = v;
        }
        float* pB = sB + buf * BSZ;
        #pragma unroll
        for (int i = 0; i < 2; i++) {
            int F = tid + i * 256;
            int r = F >> 4, c = (F & 15) * 4;
            float4 v;
            v.x = __uint_as_float(f2tf(bv[i].x));
            v.y = __uint_as_float(f2tf(bv[i].y));
            v.z = __uint_as_float(f2tf(bv[i].z));
            v.w = __uint_as_float(f2tf(bv[i].w));
            *(float4*)(pB + r * BSTRIDE + c) = v;
        }
    };

    loadA(0);
    storeT(0);
    __syncthreads();

    const int iters = K / BK;   // 8
    for (int it = 0; it < iters; it++) {
        int buf = it & 1;
        if (it + 1 < iters) loadA((it + 1) * BK);
        const float* pA = sA + buf * ASZ;
        const float* pB = sB + buf * BSZ;
        #pragma unroll
        for (int ks = 0; ks < 4; ks++) {
            int k = ks * 8;
            unsigned a[2][4], b[4][2];
            #pragma unroll
            for (int mt = 0; mt < 2; mt++) {
                int r0 = wm * 32 + mt * 16;
                a[mt][0] = __float_as_uint(pA[(r0 + g) * ASTRIDE + k + tg]);
                a[mt][1] = __float_as_uint(pA[(r0 + g + 8) * ASTRIDE + k + tg]);
                a[mt][2] = __float_as_uint(pA[(r0 + g) * ASTRIDE + k + tg + 4]);
                a[mt][3] = __float_as_uint(pA[(r0 + g + 8) * ASTRIDE + k + tg + 4]);
            }
            #pragma unroll
            for (int nt = 0; nt < 4; nt++) {
                int c0 = wn * 32 + nt * 8;
                b[nt][0] = __float_as_uint(pB[(k + tg) * BSTRIDE + c0 + g]);
                b[nt][1] = __float_as_uint(pB[(k + tg + 4) * BSTRIDE + c0 + g]);
            }
            #pragma unroll
            for (int mt = 0; mt < 2; mt++)
                #pragma unroll
                for (int nt = 0; nt < 4; nt++) {
                    asm volatile(
                        "mma.sync.aligned.m16n8k8.row.col.f32.tf32.tf32.f32 "
                        "{%0,%1,%2,%3}, {%4,%5,%6,%7}, {%8,%9}, {%0,%1,%2,%3};"
                        : "+f"(acc[mt][nt][0]), "+f"(acc[mt][nt][1]),
                          "+f"(acc[mt][nt][2]), "+f"(acc[mt][nt][3])
                        : "r"(a[mt][0]), "r"(a[mt][1]), "r"(a[mt][2]), "r"(a[mt][3]),
                          "r"(b[nt][0]), "r"(b[nt][1]));
                }
        }
        if (it + 1 < iters) storeT(buf ^ 1);
        __syncthreads();
    }

    // ---- C store ----
    #pragma unroll
    for (int mt = 0; mt < 2; mt++) {
        int r = rowBase + wm * 32 + mt * 16 + g;
        #pragma unroll
        for (int nt = 0; nt < 4; nt++) {
            int c = hh * BN + wn * 32 + nt * 8 + tg * 2;
            if (r < M)
                *(float2*)(C + (long)r * HC + c) = make_float2(acc[mt][nt][0], acc[mt][nt][1]);
            if (r + 8 < M)
                *(float2*)(C + (long)(r + 8) * HC + c) = make_float2(acc[mt][nt][2], acc[mt][nt][3]);
        }
    }

    // ---- fused attention scores ----
    float ps0[2] = {0.f, 0.f}, ps1[2] = {0.f, 0.f};
    float pd0[2] = {0.f, 0.f}, pd1[2] = {0.f, 0.f};
    #pragma unroll
    for (int nt = 0; nt < 4; nt++) {
        int lc = wn * 32 + nt * 8 + tg * 2;
        float s0 = attS[hh * HID + lc], s1 = attS[hh * HID + lc + 1];
        float d0 = attD[hh * HID + lc], d1 = attD[hh * HID + lc + 1];
        #pragma unroll
        for (int mt = 0; mt < 2; mt++) {
            ps0[mt] += acc[mt][nt][0] * s0 + acc[mt][nt][1] * s1;
            ps1[mt] += acc[mt][nt][2] * s0 + acc[mt][nt][3] * s1;
            pd0[mt] += acc[mt][nt][0] * d0 + acc[mt][nt][1] * d1;
            pd1[mt] += acc[mt][nt][2] * d0 + acc[mt][nt][3] * d1;
        }
    }
    #pragma unroll
    for (int o = 1; o <= 2; o <<= 1) {
        #pragma unroll
        for (int mt = 0; mt < 2; mt++) {
            ps0[mt] += __shfl_xor_sync(0xffffffffu, ps0[mt], o);
            ps1[mt] += __shfl_xor_sync(0xffffffffu, ps1[mt], o);
            pd0[mt] += __shfl_xor_sync(0xffffffffu, pd0[mt], o);
            pd1[mt] += __shfl_xor_sync(0xffffffffu, pd1[mt], o);
        }
    }
    if (tg == 0) {
        #pragma unroll
        for (int mt = 0; mt < 2; mt++) {
            int rl = wm * 32 + mt * 16 + g;
            sRed[wn * (BM * 2) + rl * 2]     = ps0[mt];
            sRed[wn * (BM * 2) + rl * 2 + 1] = pd0[mt];
            sRed[wn * (BM * 2) + (rl + 8) * 2]     = ps1[mt];
            sRed[wn * (BM * 2) + (rl + 8) * 2 + 1] = pd1[mt];
        }
    }
    __syncthreads();
    if (tid < BM) {
        int row = rowBase + tid;
        if (row < M) {
            g_as[row * HEADS + hh] = sRed[tid * 2] + sRed[BM * 2 + tid * 2];
            g_ad[row * HEADS + hh] = sRed[tid * 2 + 1] + sRed[BM * 2 + tid * 2 + 1];
        }
    }
}

// ---------------- CSR aggregation: warp per dst node, no atomics ----------------
__global__ void agg_csr(const float* __restrict__ hsrc, float* __restrict__ outp) {
    int d = (blockIdx.x * blockDim.x + threadIdx.x) >> 5;
    int lane = threadIdx.x & 31;
    if (d >= NN) return;
    int start = g_off[d], end = g_off[d + 1];
    float4 dv = *(const float4*)(g_ad + d * HEADS);
    float d0 = 0.f, d1 = 0.f, d2 = 0.f, d3 = 0.f;
    for (int e = start + lane; e < end; e += 32) {
        int s = g_csr[e];
        float4 sv = *(const float4*)(g_as + s * HEADS);
        float4 ex;
        float l0 = sv.x + dv.x; l0 = fmaxf(l0, 0.2f * l0); ex.x = __expf(l0);
        float l1 = sv.y + dv.y; l1 = fmaxf(l1, 0.2f * l1); ex.y = __expf(l1);
        float l2 = sv.z + dv.z; l2 = fmaxf(l2, 0.2f * l2); ex.z = __expf(l2);
        float l3 = sv.w + dv.w; l3 = fmaxf(l3, 0.2f * l3); ex.w = __expf(l3);
        *(float4*)(g_ealpha + (long)e * HEADS) = ex;
        d0 += ex.x; d1 += ex.y; d2 += ex.z; d3 += ex.w;
    }
    #pragma unroll
    for (int o = 16; o > 0; o >>= 1) {
        d0 += __shfl_xor_sync(0xffffffffu, d0, o);
        d1 += __shfl_xor_sync(0xffffffffu, d1, o);
        d2 += __shfl_xor_sync(0xffffffffu, d2, o);
        d3 += __shfl_xor_sync(0xffffffffu, d3, o);
    }
    int hh = lane >> 3;
    float den = (hh == 0) ? d0 : (hh == 1) ? d1 : (hh == 2) ? d2 : d3;
    float invh = 1.f / (den + 1e-16f);
    float4 a0 = {0.f, 0.f, 0.f, 0.f}, a1 = {0.f, 0.f, 0.f, 0.f};
    for (int e = start; e < end; e++) {
        int s = g_csr[e];
        float al = g_ealpha[(long)e * HEADS + hh] * invh;
        const float4* hp = (const float4*)(hsrc + (long)s * HC) + lane * 2;
        float4 v0 = hp[0], v1 = hp[1];
        a0.x += al * v0.x; a0.y += al * v0.y; a0.z += al * v0.z; a0.w += al * v0.w;
        a1.x += al * v1.x; a1.y += al * v1.y; a1.z += al * v1.z; a1.w += al * v1.w;
    }
    float4* op = (float4*)(outp + (long)d * HC) + lane * 2;
    op[0] = a0;
    op[1] = a1;
}

// ---------------- zero BN stats ----------------
__global__ void zero_stats() {
    int i = threadIdx.x;
    g_stats[i] = 0.f;
    g_stats[i + 256] = 0.f;
}

// ---------------- BN stats: per-channel sum & sumsq ----------------
__global__ void bn_stats(const float* __restrict__ x, const float* __restrict__ bias,
                         int N, int C) {
    int tid = threadIdx.x;
    int c = tid % C;
    int g = tid / C;
    int G = blockDim.x / C;
    int rows_per_block = (N + gridDim.x - 1) / gridDim.x;
    int r0 = blockIdx.x * rows_per_block;
    int r1 = min(N, r0 + rows_per_block);
    float b = bias ? bias[c] : 0.f;
    float s = 0.f, q = 0.f;
    for (int r = r0 + g; r < r1; r += G) {
        float v = x[(long)r * C + c] + b;
        s += v;
        q += v * v;
    }
    __shared__ float sh[512];
    sh[tid] = s;
    sh[256 + tid] = q;
    __syncthreads();
    if (g == 0) {
        for (int gg = 1; gg < G; gg++) {
            s += sh[gg * C + c];
            q += sh[256 + gg * C + c];
        }
        atomicAdd(&g_stats[c], s);
        atomicAdd(&g_stats[C + c], q);
    }
}

// ---------------- BN apply + activation (act 0 = PReLU, 1 = ELU) ----------------
__global__ void bn_apply(float* __restrict__ x, const float* __restrict__ bias,
                         const float* __restrict__ gamma, const float* __restrict__ beta,
                         int N, int C, int act, const float* __restrict__ pw) {
    int i = blockIdx.x * blockDim.x + threadIdx.x;
    if (i >= N * C) return;
    int c = i % C;
    float invN = 1.f / (float)N;
    float mean = g_stats[c] * invN;
    float var = g_stats[C + c] * invN - mean * mean;
    float inv = rsqrtf(var + 1e-5f);
    float v = x[i] + (bias ? bias[c] : 0.f);
    v = (v - mean) * inv * gamma[c] + beta[c];
    if (act == 0) {
        float w = pw[0];
        v = (v >= 0.f) ? v : w * v;
    } else {
        v = (v > 0.f) ? v : expm1f(v);
    }
    x[i] = v;
}

// ---------------- layer-2 head mean + bias ----------------
__global__ void head_mean(const float* __restrict__ b2) {
    int i = blockIdx.x * blockDim.x + threadIdx.x;
    if (i >= NN * HID) return;
    int n = i >> 6, c = i & 63;
    const float* a = g_agg + (long)n * HC;
    g_y[i] = 0.25f * (a[c] + a[64 + c] + a[128 + c] + a[192 + c]) + b2[c];
}

// ---------------- final linear [N,64] @ [64,86] + b (W in smem) ----------------
__global__ void fc_out(const float* __restrict__ W, const float* __restrict__ b,
                       float* __restrict__ out) {
    __shared__ float sW[HID * OUTD];
    for (int l = threadIdx.x; l < HID * OUTD; l += blockDim.x)
        sW[l] = W[l];
    __syncthreads();
    int i = blockIdx.x * blockDim.x + threadIdx.x;
    if (i >= NN * OUTD) return;
    int n = i / OUTD, o = i - n * OUTD;
    const float* y = g_y + (long)n * HID;
    float acc = b[o];
    #pragma unroll
    for (int k = 0; k < HID; k++) acc += y[k] * sW[k * OUTD + o];
    out[i] = acc;
}

extern "C" void kernel_launch(void* const* d_in, const int* in_sizes, int n_in,
                              void* d_out, int out_size) {
    const float* x   = (const float*)d_in[0];
    const void*  ei  = d_in[1];
    const float* W1  = (const float*)d_in[2];
    const float* as1 = (const float*)d_in[3];
    const float* ad1 = (const float*)d_in[4];
    const float* b1  = (const float*)d_in[5];
    const float* W2  = (const float*)d_in[6];
    const float* as2 = (const float*)d_in[7];
    const float* ad2 = (const float*)d_in[8];
    const float* b2  = (const float*)d_in[9];
    const float* g1  = (const float*)d_in[10];
    const float* be1 = (const float*)d_in[11];
    const float* g2  = (const float*)d_in[12];
    const float* be2 = (const float*)d_in[13];
    const float* pw  = (const float*)d_in[14];
    const float* fcW = (const float*)d_in[15];
    const float* fcb = (const float*)d_in[16];
    float* out = (float*)d_out;

    float *p_h, *p_agg, *p_y;
    cudaGetSymbolAddress((void**)&p_h, g_h);
    cudaGetSymbolAddress((void**)&p_agg, g_agg);
    cudaGetSymbolAddress((void**)&p_y, g_y);

    static int smem_set = 0;
    if (!smem_set) {
        cudaFuncSetAttribute(gemm_tf32, cudaFuncAttributeMaxDynamicSharedMemorySize,
                             GEMM_SMEM);
        smem_set = 1;
    }

    dim3 gemmGrid(HEADS, (NN + BM - 1) / BM);
    int edgeBlocks = (E2 + 255) / 256;
    int aggBlocks  = (NN * 32 + 255) / 256;

    // ---- CSR build (once, reused by both layers) ----
    detect_dtype<<<1, 32>>>((const int*)ei);
    convert_idx<<<edgeBlocks, 256>>>(ei);
    hist_deg<<<edgeBlocks, 256>>>();
    scan1<<<NBLK_SCAN, SCAN_BLK>>>();
    scan2<<<1, SCAN_BLK>>>();
    scan3<<<NBLK_SCAN, SCAN_BLK>>>();
    scatter_csr<<<edgeBlocks, 256>>>();

    // ---- layer 1 ----
    gemm_tf32<<<gemmGrid, 256, GEMM_SMEM>>>(x, W1, p_h, as1, ad1, NN);
    agg_csr<<<aggBlocks, 256>>>(p_h, p_agg);
    zero_stats<<<1, 256>>>();
    bn_stats<<<128, 256>>>(p_agg, b1, NN, HC);
    bn_apply<<<(NN * HC + 255) / 256, 256>>>(p_agg, b1, g1, be1, NN, HC, 0, pw);

    // ---- layer 2 ----
    gemm_tf32<<<gemmGrid, 256, GEMM_SMEM>>>(p_agg, W2, p_h, as2, ad2, NN);
    agg_csr<<<aggBlocks, 256>>>(p_h, p_agg);
    head_mean<<<(NN * HID + 255) / 256, 256>>>(b2);
    zero_stats<<<1, 256>>>();
    bn_stats<<<128, 256>>>(p_y, nullptr, NN, HID);
    bn_apply<<<(NN * HID + 255) / 256, 256>>>(p_y, nullptr, g2, be2, NN, HID, 1, pw);
    fc_out<<<(NN * OUTD + 255) / 256, 256>>>(fcW, fcb, out);
}

// round 5
// speedup vs baseline: 3.0003x; 1.1520x over previous
#include <cuda_runtime.h>

#define NN 50000
#define EE 800000
#define E2 850000      // EE + NN self loops
#define HC 256
#define HEADS 4
#define HID 64
#define OUTD 86
#define SCAN_BLK 256
#define NBLK_SCAN ((NN + SCAN_BLK - 1) / SCAN_BLK)   // 196

// GEMM tiling
#define BM 128
#define BN 64
#define BK 32
#define ASTRIDE 36
#define BSTRIDE 72
#define ASZ (BM * ASTRIDE)
#define BSZ (BK * BSTRIDE)
#define GEMM_SMEM ((2 * ASZ + 2 * BSZ + 2 * BM * 2) * 4)

// ---- scratch (device globals: allocation-free) ----
__device__ float g_h[NN * HC];
__device__ float g_agg[NN * HC];
__device__ float g_as[NN * HEADS];
__device__ float g_ad[NN * HEADS];
__device__ float g_ealpha[E2 * HEADS];
__device__ float g_y[NN * HID];
__device__ float g_stats[2 * HC];
__device__ float g_scale[HC];
__device__ float g_shift[HC];
__device__ int   g_src[E2];
__device__ int   g_dst[E2];
__device__ int   g_rank[E2];
__device__ int   g_deg[NN];
__device__ int   g_off[NN + 1];
__device__ int   g_bsum[SCAN_BLK];
__device__ int   g_boff[SCAN_BLK];
__device__ int   g_csr[E2];
__device__ int   g_is64;

// ---------------- dtype probe ----------------
__global__ void detect_dtype(const int* __restrict__ ei32) {
    if (threadIdx.x == 0) {
        int is64 = 1;
        for (int i = 0; i < 256; i++)
            if (ei32[2 * i + 1] != 0) { is64 = 0; break; }
        g_is64 = is64;
    }
}

// ---------------- normalize edge index + self loops; zero deg ----------------
__global__ void convert_idx(const void* __restrict__ eiv) {
    int e = blockIdx.x * blockDim.x + threadIdx.x;
    if (e < NN) g_deg[e] = 0;
    if (e >= E2) return;
    if (e >= EE) { g_src[e] = g_dst[e] = e - EE; return; }
    if (g_is64) {
        const long long* p = (const long long*)eiv;
        g_src[e] = (int)p[e];
        g_dst[e] = (int)p[EE + e];
    } else {
        const int* p = (const int*)eiv;
        g_src[e] = p[e];
        g_dst[e] = p[EE + e];
    }
}

__global__ void hist_deg() {
    int e = blockIdx.x * blockDim.x + threadIdx.x;
    if (e >= E2) return;
    g_rank[e] = atomicAdd(&g_deg[g_dst[e]], 1);
}

__global__ void scan1() {
    __shared__ int sh[SCAN_BLK];
    int t = threadIdx.x, b = blockIdx.x;
    int idx = b * SCAN_BLK + t;
    sh[t] = (idx < NN) ? g_deg[idx] : 0;
    __syncthreads();
    for (int o = 128; o > 0; o >>= 1) {
        if (t < o) sh[t] += sh[t + o];
        __syncthreads();
    }
    if (t == 0) g_bsum[b] = sh[0];
}

__global__ void scan2() {
    __shared__ int sh[SCAN_BLK];
    int t = threadIdx.x;
    sh[t] = (t < NBLK_SCAN) ? g_bsum[t] : 0;
    __syncthreads();
    int v = sh[t];
    for (int o = 1; o < SCAN_BLK; o <<= 1) {
        int u = (t >= o) ? sh[t - o] : 0;
        __syncthreads();
        sh[t] += u;
        __syncthreads();
    }
    g_boff[t] = sh[t] - v;
    if (t == 0) g_off[NN] = E2;
}

__global__ void scan3() {
    __shared__ int sh[SCAN_BLK];
    int t = threadIdx.x, b = blockIdx.x;
    int idx = b * SCAN_BLK + t;
    int v = (idx < NN) ? g_deg[idx] : 0;
    sh[t] = v;
    __syncthreads();
    for (int o = 1; o < SCAN_BLK; o <<= 1) {
        int u = (t >= o) ? sh[t - o] : 0;
        __syncthreads();
        sh[t] += u;
        __syncthreads();
    }
    if (idx < NN) g_off[idx] = g_boff[b] + sh[t] - v;
}

__global__ void scatter_csr() {
    int e = blockIdx.x * blockDim.x + threadIdx.x;
    if (e >= E2) return;
    g_csr[g_off[g_dst[e]] + g_rank[e]] = g_src[e];
}

// ---------------- TF32 tensor-core GEMM + fused BN/PReLU pre-op + attn epilogue ----------------
__device__ __forceinline__ unsigned f2tf(float x) {
    unsigned r;
    asm("cvt.rna.tf32.f32 %0, %1;" : "=r"(r) : "f"(x));
    return r;
}

__global__ __launch_bounds__(256) void gemm_tf32(
        const float* __restrict__ A, const float* __restrict__ B,
        float* __restrict__ C, const float* __restrict__ attS,
        const float* __restrict__ attD, int M,
        const float* __restrict__ scale, const float* __restrict__ shift,
        const float* __restrict__ pw) {
    extern __shared__ float sm[];
    float* sA = sm;
    float* sB = sm + 2 * ASZ;
    float* sRed = sm + 2 * ASZ + 2 * BSZ;
    const int K = 256;
    int tid = threadIdx.x, lane = tid & 31, warp = tid >> 5;
    int wm = warp >> 1, wn = warp & 1;
    int g = lane >> 2, tg = lane & 3;
    int rowBase = blockIdx.y * BM;
    int hh = blockIdx.x;
    float w = scale ? pw[0] : 0.f;

    float acc[2][4][4];
    #pragma unroll
    for (int mt = 0; mt < 2; mt++)
        #pragma unroll
        for (int nt = 0; nt < 4; nt++)
            #pragma unroll
            for (int i = 0; i < 4; i++) acc[mt][nt][i] = 0.f;

    float4 av[4], bv[2];
    auto loadA = [&](int k0) {
        #pragma unroll
        for (int i = 0; i < 4; i++) {
            int F = tid + i * 256;
            int r = rowBase + (F >> 3);
            int c = (F & 7) * 4;
            if (r < M) {
                float4 v = *(const float4*)(A + (long)r * K + k0 + c);
                if (scale) {
                    float4 sc = *(const float4*)(scale + k0 + c);
                    float4 sh = *(const float4*)(shift + k0 + c);
                    v.x = fmaf(v.x, sc.x, sh.x); v.x = (v.x >= 0.f) ? v.x : w * v.x;
                    v.y = fmaf(v.y, sc.y, sh.y); v.y = (v.y >= 0.f) ? v.y : w * v.y;
                    v.z = fmaf(v.z, sc.z, sh.z); v.z = (v.z >= 0.f) ? v.z : w * v.z;
                    v.w = fmaf(v.w, sc.w, sh.w); v.w = (v.w >= 0.f) ? v.w : w * v.w;
                }
                av[i] = v;
            } else {
                av[i] = make_float4(0.f, 0.f, 0.f, 0.f);
            }
        }
        #pragma unroll
        for (int i = 0; i < 2; i++) {
            int F = tid + i * 256;
            int r = k0 + (F >> 4);
            int c = hh * BN + (F & 15) * 4;
            bv[i] = *(const float4*)(B + (long)r * HC + c);
        }
    };
    auto storeT = [&](int buf) {
        float* pA = sA + buf * ASZ;
        #pragma unroll
        for (int i = 0; i < 4; i++) {
            int F = tid + i * 256;
            int r = F >> 3, c = (F & 7) * 4;
            float4 v;
            v.x = __uint_as_float(f2tf(av[i].x));
            v.y = __uint_as_float(f2tf(av[i].y));
            v.z = __uint_as_float(f2tf(av[i].z));
            v.w = __uint_as_float(f2tf(av[i].w));
            *(float4*)(pA + r * ASTRIDE + c) = v;
        }
        float* pB = sB + buf * BSZ;
        #pragma unroll
        for (int i = 0; i < 2; i++) {
            int F = tid + i * 256;
            int r = F >> 4, c = (F & 15) * 4;
            float4 v;
            v.x = __uint_as_float(f2tf(bv[i].x));
            v.y = __uint_as_float(f2tf(bv[i].y));
            v.z = __uint_as_float(f2tf(bv[i].z));
            v.w = __uint_as_float(f2tf(bv[i].w));
            *(float4*)(pB + r * BSTRIDE + c) = v;
        }
    };

    loadA(0);
    storeT(0);
    __syncthreads();

    const int iters = K / BK;
    for (int it = 0; it < iters; it++) {
        int buf = it & 1;
        if (it + 1 < iters) loadA((it + 1) * BK);
        const float* pA = sA + buf * ASZ;
        const float* pB = sB + buf * BSZ;
        #pragma unroll
        for (int ks = 0; ks < 4; ks++) {
            int k = ks * 8;
            unsigned a[2][4], b[4][2];
            #pragma unroll
            for (int mt = 0; mt < 2; mt++) {
                int r0 = wm * 32 + mt * 16;
                a[mt][0] = __float_as_uint(pA[(r0 + g) * ASTRIDE + k + tg]);
                a[mt][1] = __float_as_uint(pA[(r0 + g + 8) * ASTRIDE + k + tg]);
                a[mt][2] = __float_as_uint(pA[(r0 + g) * ASTRIDE + k + tg + 4]);
                a[mt][3] = __float_as_uint(pA[(r0 + g + 8) * ASTRIDE + k + tg + 4]);
            }
            #pragma unroll
            for (int nt = 0; nt < 4; nt++) {
                int c0 = wn * 32 + nt * 8;
                b[nt][0] = __float_as_uint(pB[(k + tg) * BSTRIDE + c0 + g]);
                b[nt][1] = __float_as_uint(pB[(k + tg + 4) * BSTRIDE + c0 + g]);
            }
            #pragma unroll
            for (int mt = 0; mt < 2; mt++)
                #pragma unroll
                for (int nt = 0; nt < 4; nt++) {
                    asm volatile(
                        "mma.sync.aligned.m16n8k8.row.col.f32.tf32.tf32.f32 "
                        "{%0,%1,%2,%3}, {%4,%5,%6,%7}, {%8,%9}, {%0,%1,%2,%3};"
                        : "+f"(acc[mt][nt][0]), "+f"(acc[mt][nt][1]),
                          "+f"(acc[mt][nt][2]), "+f"(acc[mt][nt][3])
                        : "r"(a[mt][0]), "r"(a[mt][1]), "r"(a[mt][2]), "r"(a[mt][3]),
                          "r"(b[nt][0]), "r"(b[nt][1]));
                }
        }
        if (it + 1 < iters) storeT(buf ^ 1);
        __syncthreads();
    }

    #pragma unroll
    for (int mt = 0; mt < 2; mt++) {
        int r = rowBase + wm * 32 + mt * 16 + g;
        #pragma unroll
        for (int nt = 0; nt < 4; nt++) {
            int c = hh * BN + wn * 32 + nt * 8 + tg * 2;
            if (r < M)
                *(float2*)(C + (long)r * HC + c) = make_float2(acc[mt][nt][0], acc[mt][nt][1]);
            if (r + 8 < M)
                *(float2*)(C + (long)(r + 8) * HC + c) = make_float2(acc[mt][nt][2], acc[mt][nt][3]);
        }
    }

    float ps0[2] = {0.f, 0.f}, ps1[2] = {0.f, 0.f};
    float pd0[2] = {0.f, 0.f}, pd1[2] = {0.f, 0.f};
    #pragma unroll
    for (int nt = 0; nt < 4; nt++) {
        int lc = wn * 32 + nt * 8 + tg * 2;
        float s0 = attS[hh * HID + lc], s1 = attS[hh * HID + lc + 1];
        float d0 = attD[hh * HID + lc], d1 = attD[hh * HID + lc + 1];
        #pragma unroll
        for (int mt = 0; mt < 2; mt++) {
            ps0[mt] += acc[mt][nt][0] * s0 + acc[mt][nt][1] * s1;
            ps1[mt] += acc[mt][nt][2] * s0 + acc[mt][nt][3] * s1;
            pd0[mt] += acc[mt][nt][0] * d0 + acc[mt][nt][1] * d1;
            pd1[mt] += acc[mt][nt][2] * d0 + acc[mt][nt][3] * d1;
        }
    }
    #pragma unroll
    for (int o = 1; o <= 2; o <<= 1) {
        #pragma unroll
        for (int mt = 0; mt < 2; mt++) {
            ps0[mt] += __shfl_xor_sync(0xffffffffu, ps0[mt], o);
            ps1[mt] += __shfl_xor_sync(0xffffffffu, ps1[mt], o);
            pd0[mt] += __shfl_xor_sync(0xffffffffu, pd0[mt], o);
            pd1[mt] += __shfl_xor_sync(0xffffffffu, pd1[mt], o);
        }
    }
    if (tg == 0) {
        #pragma unroll
        for (int mt = 0; mt < 2; mt++) {
            int rl = wm * 32 + mt * 16 + g;
            sRed[wn * (BM * 2) + rl * 2]     = ps0[mt];
            sRed[wn * (BM * 2) + rl * 2 + 1] = pd0[mt];
            sRed[wn * (BM * 2) + (rl + 8) * 2]     = ps1[mt];
            sRed[wn * (BM * 2) + (rl + 8) * 2 + 1] = pd1[mt];
        }
    }
    __syncthreads();
    if (tid < BM) {
        int row = rowBase + tid;
        if (row < M) {
            g_as[row * HEADS + hh] = sRed[tid * 2] + sRed[BM * 2 + tid * 2];
            g_ad[row * HEADS + hh] = sRed[tid * 2 + 1] + sRed[BM * 2 + tid * 2 + 1];
        }
    }
}

// ---------------- CSR aggregation: warp per dst node ----------------
__global__ void agg_csr(const float* __restrict__ hsrc, float* __restrict__ outp) {
    int d = (blockIdx.x * blockDim.x + threadIdx.x) >> 5;
    int lane = threadIdx.x & 31;
    if (d >= NN) return;
    int start = g_off[d], end = g_off[d + 1];
    float4 dv = *(const float4*)(g_ad + d * HEADS);
    float d0 = 0.f, d1 = 0.f, d2 = 0.f, d3 = 0.f;
    for (int e = start + lane; e < end; e += 32) {
        int s = g_csr[e];
        float4 sv = *(const float4*)(g_as + s * HEADS);
        float4 ex;
        float l0 = sv.x + dv.x; l0 = fmaxf(l0, 0.2f * l0); ex.x = __expf(l0);
        float l1 = sv.y + dv.y; l1 = fmaxf(l1, 0.2f * l1); ex.y = __expf(l1);
        float l2 = sv.z + dv.z; l2 = fmaxf(l2, 0.2f * l2); ex.z = __expf(l2);
        float l3 = sv.w + dv.w; l3 = fmaxf(l3, 0.2f * l3); ex.w = __expf(l3);
        *(float4*)(g_ealpha + (long)e * HEADS) = ex;
        d0 += ex.x; d1 += ex.y; d2 += ex.z; d3 += ex.w;
    }
    #pragma unroll
    for (int o = 16; o > 0; o >>= 1) {
        d0 += __shfl_xor_sync(0xffffffffu, d0, o);
        d1 += __shfl_xor_sync(0xffffffffu, d1, o);
        d2 += __shfl_xor_sync(0xffffffffu, d2, o);
        d3 += __shfl_xor_sync(0xffffffffu, d3, o);
    }
    int hh = lane >> 3;
    float den = (hh == 0) ? d0 : (hh == 1) ? d1 : (hh == 2) ? d2 : d3;
    float invh = 1.f / (den + 1e-16f);
    float4 a0 = {0.f, 0.f, 0.f, 0.f}, a1 = {0.f, 0.f, 0.f, 0.f};
    for (int e = start; e < end; e++) {
        int s = g_csr[e];
        float al = g_ealpha[(long)e * HEADS + hh] * invh;
        const float4* hp = (const float4*)(hsrc + (long)s * HC) + lane * 2;
        float4 v0 = hp[0], v1 = hp[1];
        a0.x += al * v0.x; a0.y += al * v0.y; a0.z += al * v0.z; a0.w += al * v0.w;
        a1.x += al * v1.x; a1.y += al * v1.y; a1.z += al * v1.z; a1.w += al * v1.w;
    }
    float4* op = (float4*)(outp + (long)d * HC) + lane * 2;
    op[0] = a0;
    op[1] = a1;
}

__global__ void zero_stats() {
    int i = threadIdx.x;
    g_stats[i] = 0.f;
    g_stats[i + 256] = 0.f;
}

// ---------------- BN stats (no bias: biases before BN cancel exactly) ----------------
__global__ void bn_stats(const float* __restrict__ x, int N, int C) {
    int tid = threadIdx.x;
    int c = tid % C;
    int g = tid / C;
    int G = blockDim.x / C;
    int rows_per_block = (N + gridDim.x - 1) / gridDim.x;
    int r0 = blockIdx.x * rows_per_block;
    int r1 = min(N, r0 + rows_per_block);
    float s = 0.f, q = 0.f;
    for (int r = r0 + g; r < r1; r += G) {
        float v = x[(long)r * C + c];
        s += v;
        q += v * v;
    }
    __shared__ float sh[512];
    sh[tid] = s;
    sh[256 + tid] = q;
    __syncthreads();
    if (g == 0) {
        for (int gg = 1; gg < G; gg++) {
            s += sh[gg * C + c];
            q += sh[256 + gg * C + c];
        }
        atomicAdd(&g_stats[c], s);
        atomicAdd(&g_stats[C + c], q);
    }
}

// ---------------- per-channel affine from stats ----------------
__global__ void bn_finalize(const float* __restrict__ gamma,
                            const float* __restrict__ beta, int N, int C) {
    int c = threadIdx.x;
    if (c >= C) return;
    float invN = 1.f / (float)N;
    float mean = g_stats[c] * invN;
    float var = g_stats[C + c] * invN - mean * mean;
    float sc = gamma[c] * rsqrtf(var + 1e-5f);
    g_scale[c] = sc;
    g_shift[c] = beta[c] - mean * sc;
}

// ---------------- BN apply + ELU (layer 2 path, small tensor) ----------------
__global__ void bn_apply_elu(float* __restrict__ x, const float* __restrict__ gamma,
                             const float* __restrict__ beta, int N, int C) {
    int i = blockIdx.x * blockDim.x + threadIdx.x;
    if (i >= N * C) return;
    int c = i % C;
    float invN = 1.f / (float)N;
    float mean = g_stats[c] * invN;
    float var = g_stats[C + c] * invN - mean * mean;
    float inv = rsqrtf(var + 1e-5f);
    float v = (x[i] - mean) * inv * gamma[c] + beta[c];
    v = (v > 0.f) ? v : expm1f(v);
    x[i] = v;
}

// ---------------- layer-2 head mean (b2 cancels under BN) ----------------
__global__ void head_mean() {
    int i = blockIdx.x * blockDim.x + threadIdx.x;
    if (i >= NN * HID) return;
    int n = i >> 6, c = i & 63;
    const float* a = g_agg + (long)n * HC;
    g_y[i] = 0.25f * (a[c] + a[64 + c] + a[128 + c] + a[192 + c]);
}

// ---------------- final linear (float4 row loads, W in smem) ----------------
__global__ void fc_out(const float* __restrict__ W, const float* __restrict__ b,
                       float* __restrict__ out) {
    __shared__ float sW[HID * OUTD];
    for (int l = threadIdx.x; l < HID * OUTD; l += blockDim.x)
        sW[l] = W[l];
    __syncthreads();
    int i = blockIdx.x * blockDim.x + threadIdx.x;
    if (i >= NN * OUTD) return;
    int n = i / OUTD, o = i - n * OUTD;
    const float4* y4 = (const float4*)(g_y + (long)n * HID);
    float acc = b[o];
    #pragma unroll
    for (int k = 0; k < 16; k++) {
        float4 v = y4[k];
        acc += v.x * sW[(4 * k) * OUTD + o];
        acc += v.y * sW[(4 * k + 1) * OUTD + o];
        acc += v.z * sW[(4 * k + 2) * OUTD + o];
        acc += v.w * sW[(4 * k + 3) * OUTD + o];
    }
    out[i] = acc;
}

extern "C" void kernel_launch(void* const* d_in, const int* in_sizes, int n_in,
                              void* d_out, int out_size) {
    const float* x   = (const float*)d_in[0];
    const void*  ei  = d_in[1];
    const float* W1  = (const float*)d_in[2];
    const float* as1 = (const float*)d_in[3];
    const float* ad1 = (const float*)d_in[4];
    const float* W2  = (const float*)d_in[6];
    const float* as2 = (const float*)d_in[7];
    const float* ad2 = (const float*)d_in[8];
    const float* g1  = (const float*)d_in[10];
    const float* be1 = (const float*)d_in[11];
    const float* g2  = (const float*)d_in[12];
    const float* be2 = (const float*)d_in[13];
    const float* pw  = (const float*)d_in[14];
    const float* fcW = (const float*)d_in[15];
    const float* fcb = (const float*)d_in[16];
    float* out = (float*)d_out;

    float *p_h, *p_agg, *p_y, *p_scale, *p_shift;
    cudaGetSymbolAddress((void**)&p_h, g_h);
    cudaGetSymbolAddress((void**)&p_agg, g_agg);
    cudaGetSymbolAddress((void**)&p_y, g_y);
    cudaGetSymbolAddress((void**)&p_scale, g_scale);
    cudaGetSymbolAddress((void**)&p_shift, g_shift);

    static int smem_set = 0;
    if (!smem_set) {
        cudaFuncSetAttribute(gemm_tf32, cudaFuncAttributeMaxDynamicSharedMemorySize,
                             GEMM_SMEM);
        smem_set = 1;
    }

    dim3 gemmGrid(HEADS, (NN + BM - 1) / BM);
    int edgeBlocks = (E2 + 255) / 256;
    int aggBlocks  = (NN * 32 + 255) / 256;

    // ---- CSR build ----
    detect_dtype<<<1, 32>>>((const int*)ei);
    convert_idx<<<edgeBlocks, 256>>>(ei);
    hist_deg<<<edgeBlocks, 256>>>();
    scan1<<<NBLK_SCAN, SCAN_BLK>>>();
    scan2<<<1, SCAN_BLK>>>();
    scan3<<<NBLK_SCAN, SCAN_BLK>>>();
    scatter_csr<<<edgeBlocks, 256>>>();

    // ---- layer 1 ----
    gemm_tf32<<<gemmGrid, 256, GEMM_SMEM>>>(x, W1, p_h, as1, ad1, NN,
                                            nullptr, nullptr, nullptr);
    agg_csr<<<aggBlocks, 256>>>(p_h, p_agg);
    zero_stats<<<1, 256>>>();
    bn_stats<<<512, 256>>>(p_agg, NN, HC);
    bn_finalize<<<1, 256>>>(g1, be1, NN, HC);

    // ---- layer 2 (BN1 affine + PReLU fused into A-load) ----
    gemm_tf32<<<gemmGrid, 256, GEMM_SMEM>>>(p_agg, W2, p_h, as2, ad2, NN,
                                            p_scale, p_shift, pw);
    agg_csr<<<aggBlocks, 256>>>(p_h, p_agg);
    head_mean<<<(NN * HID + 255) / 256, 256>>>();
    zero_stats<<<1, 256>>>();
    bn_stats<<<512, 256>>>(p_y, NN, HID);
    bn_apply_elu<<<(NN * HID + 255) / 256, 256>>>(p_y, g2, be2, NN, HID);
    fc_out<<<(NN * OUTD + 255) / 256, 256>>>(fcW, fcb, out);
}

// round 6
// speedup vs baseline: 3.5240x; 1.1746x over previous
#include <cuda_runtime.h>
#include <cuda_fp16.h>

#define NN 50000
#define EE 800000
#define E2 850000      // EE + NN self loops
#define HC 256
#define HEADS 4
#define HID 64
#define OUTD 86
#define SCAN_BLK 256
#define NBLK_SCAN ((NN + SCAN_BLK - 1) / SCAN_BLK)   // 196

// GEMM tiling
#define BM 128
#define BN 64
#define BK 32
#define ASTRIDE 36
#define BSTRIDE 72
#define ASZ (BM * ASTRIDE)
#define BSZ (BK * BSTRIDE)
#define GEMM_SMEM ((2 * ASZ + 2 * BSZ + 2 * BM * 2) * 4)

// ---- scratch (device globals: allocation-free) ----
__device__ __half g_h[NN * HC];         // post-GEMM features, fp16
__device__ float g_agg[NN * HC];
__device__ float g_as[NN * HEADS];
__device__ float g_ad[NN * HEADS];
__device__ float g_ealpha[E2 * HEADS];
__device__ float g_y[NN * HID];
__device__ float g_stats[2 * HC];
__device__ float g_scale[HC];
__device__ float g_shift[HC];
__device__ int   g_src[E2];
__device__ int   g_dst[E2];
__device__ int   g_rank[E2];
__device__ int   g_deg[NN];
__device__ int   g_off[NN + 1];
__device__ int   g_bsum[SCAN_BLK];
__device__ int   g_boff[SCAN_BLK];
__device__ int   g_csr[E2];
__device__ int   g_is64;

// ---------------- dtype probe ----------------
__global__ void detect_dtype(const int* __restrict__ ei32) {
    if (threadIdx.x == 0) {
        int is64 = 1;
        for (int i = 0; i < 256; i++)
            if (ei32[2 * i + 1] != 0) { is64 = 0; break; }
        g_is64 = is64;
    }
}

__global__ void convert_idx(const void* __restrict__ eiv) {
    int e = blockIdx.x * blockDim.x + threadIdx.x;
    if (e < NN) g_deg[e] = 0;
    if (e >= E2) return;
    if (e >= EE) { g_src[e] = g_dst[e] = e - EE; return; }
    if (g_is64) {
        const long long* p = (const long long*)eiv;
        g_src[e] = (int)p[e];
        g_dst[e] = (int)p[EE + e];
    } else {
        const int* p = (const int*)eiv;
        g_src[e] = p[e];
        g_dst[e] = p[EE + e];
    }
}

__global__ void hist_deg() {
    int e = blockIdx.x * blockDim.x + threadIdx.x;
    if (e >= E2) return;
    g_rank[e] = atomicAdd(&g_deg[g_dst[e]], 1);
}

__global__ void scan1() {
    __shared__ int sh[SCAN_BLK];
    int t = threadIdx.x, b = blockIdx.x;
    int idx = b * SCAN_BLK + t;
    sh[t] = (idx < NN) ? g_deg[idx] : 0;
    __syncthreads();
    for (int o = 128; o > 0; o >>= 1) {
        if (t < o) sh[t] += sh[t + o];
        __syncthreads();
    }
    if (t == 0) g_bsum[b] = sh[0];
}

__global__ void scan2() {
    __shared__ int sh[SCAN_BLK];
    int t = threadIdx.x;
    sh[t] = (t < NBLK_SCAN) ? g_bsum[t] : 0;
    __syncthreads();
    int v = sh[t];
    for (int o = 1; o < SCAN_BLK; o <<= 1) {
        int u = (t >= o) ? sh[t - o] : 0;
        __syncthreads();
        sh[t] += u;
        __syncthreads();
    }
    g_boff[t] = sh[t] - v;
    if (t == 0) g_off[NN] = E2;
}

__global__ void scan3() {
    __shared__ int sh[SCAN_BLK];
    int t = threadIdx.x, b = blockIdx.x;
    int idx = b * SCAN_BLK + t;
    int v = (idx < NN) ? g_deg[idx] : 0;
    sh[t] = v;
    __syncthreads();
    for (int o = 1; o < SCAN_BLK; o <<= 1) {
        int u = (t >= o) ? sh[t - o] : 0;
        __syncthreads();
        sh[t] += u;
        __syncthreads();
    }
    if (idx < NN) g_off[idx] = g_boff[b] + sh[t] - v;
}

__global__ void scatter_csr() {
    int e = blockIdx.x * blockDim.x + threadIdx.x;
    if (e >= E2) return;
    g_csr[g_off[g_dst[e]] + g_rank[e]] = g_src[e];
}

// ---------------- TF32 tensor-core GEMM + fused BN/PReLU pre-op + attn epilogue ----------------
__device__ __forceinline__ unsigned f2tf(float x) {
    unsigned r;
    asm("cvt.rna.tf32.f32 %0, %1;" : "=r"(r) : "f"(x));
    return r;
}

__global__ __launch_bounds__(256) void gemm_tf32(
        const float* __restrict__ A, const float* __restrict__ B,
        __half* __restrict__ C, const float* __restrict__ attS,
        const float* __restrict__ attD, int M,
        const float* __restrict__ scale, const float* __restrict__ shift,
        const float* __restrict__ pw) {
    extern __shared__ float sm[];
    float* sA = sm;
    float* sB = sm + 2 * ASZ;
    float* sRed = sm + 2 * ASZ + 2 * BSZ;
    const int K = 256;
    int tid = threadIdx.x, lane = tid & 31, warp = tid >> 5;
    int wm = warp >> 1, wn = warp & 1;
    int g = lane >> 2, tg = lane & 3;
    int rowBase = blockIdx.y * BM;
    int hh = blockIdx.x;
    float w = scale ? pw[0] : 0.f;

    float acc[2][4][4];
    #pragma unroll
    for (int mt = 0; mt < 2; mt++)
        #pragma unroll
        for (int nt = 0; nt < 4; nt++)
            #pragma unroll
            for (int i = 0; i < 4; i++) acc[mt][nt][i] = 0.f;

    float4 av[4], bv[2];
    auto loadA = [&](int k0) {
        #pragma unroll
        for (int i = 0; i < 4; i++) {
            int F = tid + i * 256;
            int r = rowBase + (F >> 3);
            int c = (F & 7) * 4;
            if (r < M) {
                float4 v = *(const float4*)(A + (long)r * K + k0 + c);
                if (scale) {
                    float4 sc = *(const float4*)(scale + k0 + c);
                    float4 sh = *(const float4*)(shift + k0 + c);
                    v.x = fmaf(v.x, sc.x, sh.x); v.x = (v.x >= 0.f) ? v.x : w * v.x;
                    v.y = fmaf(v.y, sc.y, sh.y); v.y = (v.y >= 0.f) ? v.y : w * v.y;
                    v.z = fmaf(v.z, sc.z, sh.z); v.z = (v.z >= 0.f) ? v.z : w * v.z;
                    v.w = fmaf(v.w, sc.w, sh.w); v.w = (v.w >= 0.f) ? v.w : w * v.w;
                }
                av[i] = v;
            } else {
                av[i] = make_float4(0.f, 0.f, 0.f, 0.f);
            }
        }
        #pragma unroll
        for (int i = 0; i < 2; i++) {
            int F = tid + i * 256;
            int r = k0 + (F >> 4);
            int c = hh * BN + (F & 15) * 4;
            bv[i] = *(const float4*)(B + (long)r * HC + c);
        }
    };
    auto storeT = [&](int buf) {
        float* pA = sA + buf * ASZ;
        #pragma unroll
        for (int i = 0; i < 4; i++) {
            int F = tid + i * 256;
            int r = F >> 3, c = (F & 7) * 4;
            float4 v;
            v.x = __uint_as_float(f2tf(av[i].x));
            v.y = __uint_as_float(f2tf(av[i].y));
            v.z = __uint_as_float(f2tf(av[i].z));
            v.w = __uint_as_float(f2tf(av[i].w));
            *(float4*)(pA + r * ASTRIDE + c) = v;
        }
        float* pB = sB + buf * BSZ;
        #pragma unroll
        for (int i = 0; i < 2; i++) {
            int F = tid + i * 256;
            int r = F >> 4, c = (F & 15) * 4;
            float4 v;
            v.x = __uint_as_float(f2tf(bv[i].x));
            v.y = __uint_as_float(f2tf(bv[i].y));
            v.z = __uint_as_float(f2tf(bv[i].z));
            v.w = __uint_as_float(f2tf(bv[i].w));
            *(float4*)(pB + r * BSTRIDE + c) = v;
        }
    };

    loadA(0);
    storeT(0);
    __syncthreads();

    const int iters = K / BK;
    for (int it = 0; it < iters; it++) {
        int buf = it & 1;
        if (it + 1 < iters) loadA((it + 1) * BK);
        const float* pA = sA + buf * ASZ;
        const float* pB = sB + buf * BSZ;
        #pragma unroll
        for (int ks = 0; ks < 4; ks++) {
            int k = ks * 8;
            unsigned a[2][4], b[4][2];
            #pragma unroll
            for (int mt = 0; mt < 2; mt++) {
                int r0 = wm * 32 + mt * 16;
                a[mt][0] = __float_as_uint(pA[(r0 + g) * ASTRIDE + k + tg]);
                a[mt][1] = __float_as_uint(pA[(r0 + g + 8) * ASTRIDE + k + tg]);
                a[mt][2] = __float_as_uint(pA[(r0 + g) * ASTRIDE + k + tg + 4]);
                a[mt][3] = __float_as_uint(pA[(r0 + g + 8) * ASTRIDE + k + tg + 4]);
            }
            #pragma unroll
            for (int nt = 0; nt < 4; nt++) {
                int c0 = wn * 32 + nt * 8;
                b[nt][0] = __float_as_uint(pB[(k + tg) * BSTRIDE + c0 + g]);
                b[nt][1] = __float_as_uint(pB[(k + tg + 4) * BSTRIDE + c0 + g]);
            }
            #pragma unroll
            for (int mt = 0; mt < 2; mt++)
                #pragma unroll
                for (int nt = 0; nt < 4; nt++) {
                    asm volatile(
                        "mma.sync.aligned.m16n8k8.row.col.f32.tf32.tf32.f32 "
                        "{%0,%1,%2,%3}, {%4,%5,%6,%7}, {%8,%9}, {%0,%1,%2,%3};"
                        : "+f"(acc[mt][nt][0]), "+f"(acc[mt][nt][1]),
                          "+f"(acc[mt][nt][2]), "+f"(acc[mt][nt][3])
                        : "r"(a[mt][0]), "r"(a[mt][1]), "r"(a[mt][2]), "r"(a[mt][3]),
                          "r"(b[nt][0]), "r"(b[nt][1]));
                }
        }
        if (it + 1 < iters) storeT(buf ^ 1);
        __syncthreads();
    }

    // ---- C store (fp16) ----
    #pragma unroll
    for (int mt = 0; mt < 2; mt++) {
        int r = rowBase + wm * 32 + mt * 16 + g;
        #pragma unroll
        for (int nt = 0; nt < 4; nt++) {
            int c = hh * BN + wn * 32 + nt * 8 + tg * 2;
            if (r < M)
                *(__half2*)(C + (long)r * HC + c) =
                    __floats2half2_rn(acc[mt][nt][0], acc[mt][nt][1]);
            if (r + 8 < M)
                *(__half2*)(C + (long)(r + 8) * HC + c) =
                    __floats2half2_rn(acc[mt][nt][2], acc[mt][nt][3]);
        }
    }

    // ---- fused attention scores (fp32 accs) ----
    float ps0[2] = {0.f, 0.f}, ps1[2] = {0.f, 0.f};
    float pd0[2] = {0.f, 0.f}, pd1[2] = {0.f, 0.f};
    #pragma unroll
    for (int nt = 0; nt < 4; nt++) {
        int lc = wn * 32 + nt * 8 + tg * 2;
        float s0 = attS[hh * HID + lc], s1 = attS[hh * HID + lc + 1];
        float d0 = attD[hh * HID + lc], d1 = attD[hh * HID + lc + 1];
        #pragma unroll
        for (int mt = 0; mt < 2; mt++) {
            ps0[mt] += acc[mt][nt][0] * s0 + acc[mt][nt][1] * s1;
            ps1[mt] += acc[mt][nt][2] * s0 + acc[mt][nt][3] * s1;
            pd0[mt] += acc[mt][nt][0] * d0 + acc[mt][nt][1] * d1;
            pd1[mt] += acc[mt][nt][2] * d0 + acc[mt][nt][3] * d1;
        }
    }
    #pragma unroll
    for (int o = 1; o <= 2; o <<= 1) {
        #pragma unroll
        for (int mt = 0; mt < 2; mt++) {
            ps0[mt] += __shfl_xor_sync(0xffffffffu, ps0[mt], o);
            ps1[mt] += __shfl_xor_sync(0xffffffffu, ps1[mt], o);
            pd0[mt] += __shfl_xor_sync(0xffffffffu, pd0[mt], o);
            pd1[mt] += __shfl_xor_sync(0xffffffffu, pd1[mt], o);
        }
    }
    if (tg == 0) {
        #pragma unroll
        for (int mt = 0; mt < 2; mt++) {
            int rl = wm * 32 + mt * 16 + g;
            sRed[wn * (BM * 2) + rl * 2]     = ps0[mt];
            sRed[wn * (BM * 2) + rl * 2 + 1] = pd0[mt];
            sRed[wn * (BM * 2) + (rl + 8) * 2]     = ps1[mt];
            sRed[wn * (BM * 2) + (rl + 8) * 2 + 1] = pd1[mt];
        }
    }
    __syncthreads();
    if (tid < BM) {
        int row = rowBase + tid;
        if (row < M) {
            g_as[row * HEADS + hh] = sRed[tid * 2] + sRed[BM * 2 + tid * 2];
            g_ad[row * HEADS + hh] = sRed[tid * 2 + 1] + sRed[BM * 2 + tid * 2 + 1];
        }
    }
}

// ---------------- CSR aggregation: warp per dst node, fp16 features ----------------
__device__ __forceinline__ void fma8(float* a, float al, uint4 v) {
    float2 f0 = __half22float2(*(__half2*)&v.x);
    float2 f1 = __half22float2(*(__half2*)&v.y);
    float2 f2 = __half22float2(*(__half2*)&v.z);
    float2 f3 = __half22float2(*(__half2*)&v.w);
    a[0] = fmaf(al, f0.x, a[0]); a[1] = fmaf(al, f0.y, a[1]);
    a[2] = fmaf(al, f1.x, a[2]); a[3] = fmaf(al, f1.y, a[3]);
    a[4] = fmaf(al, f2.x, a[4]); a[5] = fmaf(al, f2.y, a[5]);
    a[6] = fmaf(al, f3.x, a[6]); a[7] = fmaf(al, f3.y, a[7]);
}

__global__ void agg_csr(const __half* __restrict__ hsrc, float* __restrict__ outp) {
    int d = (blockIdx.x * blockDim.x + threadIdx.x) >> 5;
    int lane = threadIdx.x & 31;
    if (d >= NN) return;
    int start = g_off[d], end = g_off[d + 1];
    float4 dv = *(const float4*)(g_ad + d * HEADS);
    float d0 = 0.f, d1 = 0.f, d2 = 0.f, d3 = 0.f;
    for (int e = start + lane; e < end; e += 32) {
        int s = g_csr[e];
        float4 sv = *(const float4*)(g_as + s * HEADS);
        float4 ex;
        float l0 = sv.x + dv.x; l0 = fmaxf(l0, 0.2f * l0); ex.x = __expf(l0);
        float l1 = sv.y + dv.y; l1 = fmaxf(l1, 0.2f * l1); ex.y = __expf(l1);
        float l2 = sv.z + dv.z; l2 = fmaxf(l2, 0.2f * l2); ex.z = __expf(l2);
        float l3 = sv.w + dv.w; l3 = fmaxf(l3, 0.2f * l3); ex.w = __expf(l3);
        *(float4*)(g_ealpha + (long)e * HEADS) = ex;
        d0 += ex.x; d1 += ex.y; d2 += ex.z; d3 += ex.w;
    }
    #pragma unroll
    for (int o = 16; o > 0; o >>= 1) {
        d0 += __shfl_xor_sync(0xffffffffu, d0, o);
        d1 += __shfl_xor_sync(0xffffffffu, d1, o);
        d2 += __shfl_xor_sync(0xffffffffu, d2, o);
        d3 += __shfl_xor_sync(0xffffffffu, d3, o);
    }
    int hh = lane >> 3;            // lane covers channels [lane*8, lane*8+8)
    float den = (hh == 0) ? d0 : (hh == 1) ? d1 : (hh == 2) ? d2 : d3;
    float invh = 1.f / (den + 1e-16f);
    float a[8] = {0.f, 0.f, 0.f, 0.f, 0.f, 0.f, 0.f, 0.f};
    int e = start;
    for (; e + 2 <= end; e += 2) {
        int s0 = g_csr[e], s1 = g_csr[e + 1];
        float w0 = g_ealpha[(long)e * HEADS + hh];
        float w1 = g_ealpha[(long)(e + 1) * HEADS + hh];
        uint4 v0 = *((const uint4*)(hsrc + (long)s0 * HC) + lane);
        uint4 v1 = *((const uint4*)(hsrc + (long)s1 * HC) + lane);
        fma8(a, w0, v0);
        fma8(a, w1, v1);
    }
    if (e < end) {
        int s0 = g_csr[e];
        float w0 = g_ealpha[(long)e * HEADS + hh];
        uint4 v0 = *((const uint4*)(hsrc + (long)s0 * HC) + lane);
        fma8(a, w0, v0);
    }
    float4* op = (float4*)(outp + (long)d * HC) + lane * 2;
    op[0] = make_float4(a[0] * invh, a[1] * invh, a[2] * invh, a[3] * invh);
    op[1] = make_float4(a[4] * invh, a[5] * invh, a[6] * invh, a[7] * invh);
}

__global__ void zero_stats() {
    int i = threadIdx.x;
    g_stats[i] = 0.f;
    g_stats[i + 256] = 0.f;
}

__global__ void bn_stats(const float* __restrict__ x, int N, int C) {
    int tid = threadIdx.x;
    int c = tid % C;
    int g = tid / C;
    int G = blockDim.x / C;
    int rows_per_block = (N + gridDim.x - 1) / gridDim.x;
    int r0 = blockIdx.x * rows_per_block;
    int r1 = min(N, r0 + rows_per_block);
    float s = 0.f, q = 0.f;
    for (int r = r0 + g; r < r1; r += G) {
        float v = x[(long)r * C + c];
        s += v;
        q += v * v;
    }
    __shared__ float sh[512];
    sh[tid] = s;
    sh[256 + tid] = q;
    __syncthreads();
    if (g == 0) {
        for (int gg = 1; gg < G; gg++) {
            s += sh[gg * C + c];
            q += sh[256 + gg * C + c];
        }
        atomicAdd(&g_stats[c], s);
        atomicAdd(&g_stats[C + c], q);
    }
}

__global__ void bn_finalize(const float* __restrict__ gamma,
                            const float* __restrict__ beta, int N, int C) {
    int c = threadIdx.x;
    if (c >= C) return;
    float invN = 1.f / (float)N;
    float mean = g_stats[c] * invN;
    float var = g_stats[C + c] * invN - mean * mean;
    float sc = gamma[c] * rsqrtf(var + 1e-5f);
    g_scale[c] = sc;
    g_shift[c] = beta[c] - mean * sc;
}

__global__ void bn_apply_elu(float* __restrict__ x, const float* __restrict__ gamma,
                             const float* __restrict__ beta, int N, int C) {
    int i = blockIdx.x * blockDim.x + threadIdx.x;
    if (i >= N * C) return;
    int c = i % C;
    float invN = 1.f / (float)N;
    float mean = g_stats[c] * invN;
    float var = g_stats[C + c] * invN - mean * mean;
    float inv = rsqrtf(var + 1e-5f);
    float v = (x[i] - mean) * inv * gamma[c] + beta[c];
    v = (v > 0.f) ? v : expm1f(v);
    x[i] = v;
}

__global__ void head_mean() {
    int i = blockIdx.x * blockDim.x + threadIdx.x;
    if (i >= NN * HID) return;
    int n = i >> 6, c = i & 63;
    const float* a = g_agg + (long)n * HC;
    g_y[i] = 0.25f * (a[c] + a[64 + c] + a[128 + c] + a[192 + c]);
}

__global__ void fc_out(const float* __restrict__ W, const float* __restrict__ b,
                       float* __restrict__ out) {
    __shared__ float sW[HID * OUTD];
    for (int l = threadIdx.x; l < HID * OUTD; l += blockDim.x)
        sW[l] = W[l];
    __syncthreads();
    int i = blockIdx.x * blockDim.x + threadIdx.x;
    if (i >= NN * OUTD) return;
    int n = i / OUTD, o = i - n * OUTD;
    const float4* y4 = (const float4*)(g_y + (long)n * HID);
    float acc = b[o];
    #pragma unroll
    for (int k = 0; k < 16; k++) {
        float4 v = y4[k];
        acc += v.x * sW[(4 * k) * OUTD + o];
        acc += v.y * sW[(4 * k + 1) * OUTD + o];
        acc += v.z * sW[(4 * k + 2) * OUTD + o];
        acc += v.w * sW[(4 * k + 3) * OUTD + o];
    }
    out[i] = acc;
}

extern "C" void kernel_launch(void* const* d_in, const int* in_sizes, int n_in,
                              void* d_out, int out_size) {
    const float* x   = (const float*)d_in[0];
    const void*  ei  = d_in[1];
    const float* W1  = (const float*)d_in[2];
    const float* as1 = (const float*)d_in[3];
    const float* ad1 = (const float*)d_in[4];
    const float* W2  = (const float*)d_in[6];
    const float* as2 = (const float*)d_in[7];
    const float* ad2 = (const float*)d_in[8];
    const float* g1  = (const float*)d_in[10];
    const float* be1 = (const float*)d_in[11];
    const float* g2  = (const float*)d_in[12];
    const float* be2 = (const float*)d_in[13];
    const float* pw  = (const float*)d_in[14];
    const float* fcW = (const float*)d_in[15];
    const float* fcb = (const float*)d_in[16];
    float* out = (float*)d_out;

    __half* p_h;
    float *p_agg, *p_y, *p_scale, *p_shift;
    cudaGetSymbolAddress((void**)&p_h, g_h);
    cudaGetSymbolAddress((void**)&p_agg, g_agg);
    cudaGetSymbolAddress((void**)&p_y, g_y);
    cudaGetSymbolAddress((void**)&p_scale, g_scale);
    cudaGetSymbolAddress((void**)&p_shift, g_shift);

    static int smem_set = 0;
    if (!smem_set) {
        cudaFuncSetAttribute(gemm_tf32, cudaFuncAttributeMaxDynamicSharedMemorySize,
                             GEMM_SMEM);
        smem_set = 1;
    }

    dim3 gemmGrid(HEADS, (NN + BM - 1) / BM);
    int edgeBlocks = (E2 + 255) / 256;
    int aggBlocks  = (NN * 32 + 255) / 256;

    // ---- CSR build ----
    detect_dtype<<<1, 32>>>((const int*)ei);
    convert_idx<<<edgeBlocks, 256>>>(ei);
    hist_deg<<<edgeBlocks, 256>>>();
    scan1<<<NBLK_SCAN, SCAN_BLK>>>();
    scan2<<<1, SCAN_BLK>>>();
    scan3<<<NBLK_SCAN, SCAN_BLK>>>();
    scatter_csr<<<edgeBlocks, 256>>>();

    // ---- layer 1 ----
    gemm_tf32<<<gemmGrid, 256, GEMM_SMEM>>>(x, W1, p_h, as1, ad1, NN,
                                            nullptr, nullptr, nullptr);
    agg_csr<<<aggBlocks, 256>>>(p_h, p_agg);
    zero_stats<<<1, 256>>>();
    bn_stats<<<512, 256>>>(p_agg, NN, HC);
    bn_finalize<<<1, 256>>>(g1, be1, NN, HC);

    // ---- layer 2 (BN1 affine + PReLU fused into A-load) ----
    gemm_tf32<<<gemmGrid, 256, GEMM_SMEM>>>(p_agg, W2, p_h, as2, ad2, NN,
                                            p_scale, p_shift, pw);
    agg_csr<<<aggBlocks, 256>>>(p_h, p_agg);
    head_mean<<<(NN * HID + 255) / 256, 256>>>();
    zero_stats<<<1, 256>>>();
    bn_stats<<<512, 256>>>(p_y, NN, HID);
    bn_apply_elu<<<(NN * HID + 255) / 256, 256>>>(p_y, g2, be2, NN, HID);
    fc_out<<<(NN * OUTD + 255) / 256, 256>>>(fcW, fcb, out);
}

// round 7
// speedup vs baseline: 3.6953x; 1.0486x over previous
#include <cuda_runtime.h>
#include <cuda_fp16.h>

#define NN 50000
#define EE 800000
#define E2 850000      // EE + NN self loops
#define HC 256
#define HEADS 4
#define HID 64
#define OUTD 86
#define SCAN_BLK 256
#define NBLK_SCAN ((NN + SCAN_BLK - 1) / SCAN_BLK)   // 196

// GEMM tiling: 128x128 block tile (2 heads), 8 warps of 32x64
#define BM 128
#define BNT 128
#define BK 32
#define ASTRIDE 36
#define BSTRIDE 136
#define ASZ (BM * ASTRIDE)
#define BSZ (BK * BSTRIDE)
#define GEMM_SMEM ((2 * ASZ + 2 * BSZ) * 4)

// ---- scratch (device globals: allocation-free) ----
__device__ __half g_h[NN * HC];         // post-GEMM features, fp16
__device__ float g_agg[NN * HC];
__device__ float g_as[NN * HEADS];
__device__ float g_ad[NN * HEADS];
__device__ float g_y[NN * HID];
__device__ float g_stats[2 * HC];
__device__ float g_scale[HC];
__device__ float g_shift[HC];
__device__ int   g_src[E2];
__device__ int   g_dst[E2];
__device__ int   g_rank[E2];
__device__ int   g_deg[NN];
__device__ int   g_off[NN + 1];
__device__ int   g_bsum[SCAN_BLK];
__device__ int   g_boff[SCAN_BLK];
__device__ int   g_csr[E2];
__device__ int   g_is64;

// ---------------- dtype probe (parallel) ----------------
__global__ void detect_dtype(const int* __restrict__ ei32) {
    __shared__ int any;
    int t = threadIdx.x;
    if (t == 0) any = 0;
    __syncthreads();
    if (ei32[2 * t + 1] != 0) any = 1;
    __syncthreads();
    if (t == 0) g_is64 = !any;
}

__global__ void convert_idx(const void* __restrict__ eiv) {
    int e = blockIdx.x * blockDim.x + threadIdx.x;
    if (e < NN) g_deg[e] = 0;
    if (e >= E2) return;
    if (e >= EE) { g_src[e] = g_dst[e] = e - EE; return; }
    if (g_is64) {
        const long long* p = (const long long*)eiv;
        g_src[e] = (int)p[e];
        g_dst[e] = (int)p[EE + e];
    } else {
        const int* p = (const int*)eiv;
        g_src[e] = p[e];
        g_dst[e] = p[EE + e];
    }
}

__global__ void hist_deg() {
    int e = blockIdx.x * blockDim.x + threadIdx.x;
    if (e >= E2) return;
    g_rank[e] = atomicAdd(&g_deg[g_dst[e]], 1);
}

__global__ void scan1() {
    __shared__ int sh[SCAN_BLK];
    int t = threadIdx.x, b = blockIdx.x;
    int idx = b * SCAN_BLK + t;
    sh[t] = (idx < NN) ? g_deg[idx] : 0;
    __syncthreads();
    for (int o = 128; o > 0; o >>= 1) {
        if (t < o) sh[t] += sh[t + o];
        __syncthreads();
    }
    if (t == 0) g_bsum[b] = sh[0];
}

__global__ void scan2() {
    __shared__ int sh[SCAN_BLK];
    int t = threadIdx.x;
    sh[t] = (t < NBLK_SCAN) ? g_bsum[t] : 0;
    __syncthreads();
    int v = sh[t];
    for (int o = 1; o < SCAN_BLK; o <<= 1) {
        int u = (t >= o) ? sh[t - o] : 0;
        __syncthreads();
        sh[t] += u;
        __syncthreads();
    }
    g_boff[t] = sh[t] - v;
    if (t == 0) g_off[NN] = E2;
}

__global__ void scan3() {
    __shared__ int sh[SCAN_BLK];
    int t = threadIdx.x, b = blockIdx.x;
    int idx = b * SCAN_BLK + t;
    int v = (idx < NN) ? g_deg[idx] : 0;
    sh[t] = v;
    __syncthreads();
    for (int o = 1; o < SCAN_BLK; o <<= 1) {
        int u = (t >= o) ? sh[t - o] : 0;
        __syncthreads();
        sh[t] += u;
        __syncthreads();
    }
    if (idx < NN) g_off[idx] = g_boff[b] + sh[t] - v;
}

__global__ void scatter_csr() {
    int e = blockIdx.x * blockDim.x + threadIdx.x;
    if (e >= E2) return;
    g_csr[g_off[g_dst[e]] + g_rank[e]] = g_src[e];
}

// ---------------- TF32 GEMM 128x128 + fused BN/PReLU pre-op + attn epilogue ----------------
__device__ __forceinline__ unsigned f2tf(float x) {
    unsigned r;
    asm("cvt.rna.tf32.f32 %0, %1;" : "=r"(r) : "f"(x));
    return r;
}

__global__ __launch_bounds__(256) void gemm_tf32(
        const float* __restrict__ A, const float* __restrict__ B,
        __half* __restrict__ C, const float* __restrict__ attS,
        const float* __restrict__ attD, int M,
        const float* __restrict__ scale, const float* __restrict__ shift,
        const float* __restrict__ pw) {
    extern __shared__ float sm[];
    float* sA = sm;
    float* sB = sm + 2 * ASZ;
    const int K = 256;
    int tid = threadIdx.x, lane = tid & 31, warp = tid >> 5;
    int wm = warp >> 1, wn = warp & 1;   // 4x2 warps, 32x64 per warp
    int g = lane >> 2, tg = lane & 3;
    int rowBase = blockIdx.y * BM;
    int colBase = blockIdx.x * BNT;
    int head = blockIdx.x * 2 + wn;      // each warp owns a full head
    float w = scale ? pw[0] : 0.f;

    float acc[2][8][4];
    #pragma unroll
    for (int mt = 0; mt < 2; mt++)
        #pragma unroll
        for (int nt = 0; nt < 8; nt++)
            #pragma unroll
            for (int i = 0; i < 4; i++) acc[mt][nt][i] = 0.f;

    float4 av[4], bv[4];
    auto loadA = [&](int k0) {
        #pragma unroll
        for (int i = 0; i < 4; i++) {
            int F = tid + i * 256;
            int r = rowBase + (F >> 3);
            int c = (F & 7) * 4;
            if (r < M) {
                float4 v = *(const float4*)(A + (long)r * K + k0 + c);
                if (scale) {
                    float4 sc = *(const float4*)(scale + k0 + c);
                    float4 sh = *(const float4*)(shift + k0 + c);
                    v.x = fmaf(v.x, sc.x, sh.x); v.x = (v.x >= 0.f) ? v.x : w * v.x;
                    v.y = fmaf(v.y, sc.y, sh.y); v.y = (v.y >= 0.f) ? v.y : w * v.y;
                    v.z = fmaf(v.z, sc.z, sh.z); v.z = (v.z >= 0.f) ? v.z : w * v.z;
                    v.w = fmaf(v.w, sc.w, sh.w); v.w = (v.w >= 0.f) ? v.w : w * v.w;
                }
                av[i] = v;
            } else {
                av[i] = make_float4(0.f, 0.f, 0.f, 0.f);
            }
        }
        #pragma unroll
        for (int i = 0; i < 4; i++) {
            int F = tid + i * 256;
            int r = k0 + (F >> 5);
            int c = colBase + (F & 31) * 4;
            bv[i] = *(const float4*)(B + (long)r * HC + c);
        }
    };
    auto storeT = [&](int buf) {
        float* pA = sA + buf * ASZ;
        #pragma unroll
        for (int i = 0; i < 4; i++) {
            int F = tid + i * 256;
            int r = F >> 3, c = (F & 7) * 4;
            float4 v;
            v.x = __uint_as_float(f2tf(av[i].x));
            v.y = __uint_as_float(f2tf(av[i].y));
            v.z = __uint_as_float(f2tf(av[i].z));
            v.w = __uint_as_float(f2tf(av[i].w));
            *(float4*)(pA + r * ASTRIDE + c) = v;
        }
        float* pB = sB + buf * BSZ;
        #pragma unroll
        for (int i = 0; i < 4; i++) {
            int F = tid + i * 256;
            int r = F >> 5, c = (F & 31) * 4;
            float4 v;
            v.x = __uint_as_float(f2tf(bv[i].x));
            v.y = __uint_as_float(f2tf(bv[i].y));
            v.z = __uint_as_float(f2tf(bv[i].z));
            v.w = __uint_as_float(f2tf(bv[i].w));
            *(float4*)(pB + r * BSTRIDE + c) = v;
        }
    };

    loadA(0);
    storeT(0);
    __syncthreads();

    const int iters = K / BK;
    for (int it = 0; it < iters; it++) {
        int buf = it & 1;
        if (it + 1 < iters) loadA((it + 1) * BK);
        const float* pA = sA + buf * ASZ;
        const float* pB = sB + buf * BSZ;
        #pragma unroll
        for (int ks = 0; ks < 4; ks++) {
            int k = ks * 8;
            unsigned a[2][4], b[8][2];
            #pragma unroll
            for (int mt = 0; mt < 2; mt++) {
                int r0 = wm * 32 + mt * 16;
                a[mt][0] = __float_as_uint(pA[(r0 + g) * ASTRIDE + k + tg]);
                a[mt][1] = __float_as_uint(pA[(r0 + g + 8) * ASTRIDE + k + tg]);
                a[mt][2] = __float_as_uint(pA[(r0 + g) * ASTRIDE + k + tg + 4]);
                a[mt][3] = __float_as_uint(pA[(r0 + g + 8) * ASTRIDE + k + tg + 4]);
            }
            #pragma unroll
            for (int nt = 0; nt < 8; nt++) {
                int c0 = wn * 64 + nt * 8;
                b[nt][0] = __float_as_uint(pB[(k + tg) * BSTRIDE + c0 + g]);
                b[nt][1] = __float_as_uint(pB[(k + tg + 4) * BSTRIDE + c0 + g]);
            }
            #pragma unroll
            for (int mt = 0; mt < 2; mt++)
                #pragma unroll
                for (int nt = 0; nt < 8; nt++) {
                    asm volatile(
                        "mma.sync.aligned.m16n8k8.row.col.f32.tf32.tf32.f32 "
                        "{%0,%1,%2,%3}, {%4,%5,%6,%7}, {%8,%9}, {%0,%1,%2,%3};"
                        : "+f"(acc[mt][nt][0]), "+f"(acc[mt][nt][1]),
                          "+f"(acc[mt][nt][2]), "+f"(acc[mt][nt][3])
                        : "r"(a[mt][0]), "r"(a[mt][1]), "r"(a[mt][2]), "r"(a[mt][3]),
                          "r"(b[nt][0]), "r"(b[nt][1]));
                }
        }
        if (it + 1 < iters) storeT(buf ^ 1);
        __syncthreads();
    }

    // ---- C store (fp16) ----
    #pragma unroll
    for (int mt = 0; mt < 2; mt++) {
        int r = rowBase + wm * 32 + mt * 16 + g;
        #pragma unroll
        for (int nt = 0; nt < 8; nt++) {
            int c = colBase + wn * 64 + nt * 8 + tg * 2;
            if (r < M)
                *(__half2*)(C + (long)r * HC + c) =
                    __floats2half2_rn(acc[mt][nt][0], acc[mt][nt][1]);
            if (r + 8 < M)
                *(__half2*)(C + (long)(r + 8) * HC + c) =
                    __floats2half2_rn(acc[mt][nt][2], acc[mt][nt][3]);
        }
    }

    // ---- fused attention scores: warp-local (each warp owns one head) ----
    float ps0[2] = {0.f, 0.f}, ps1[2] = {0.f, 0.f};
    float pd0[2] = {0.f, 0.f}, pd1[2] = {0.f, 0.f};
    #pragma unroll
    for (int nt = 0; nt < 8; nt++) {
        int lc = nt * 8 + tg * 2;         // column within head
        float s0 = attS[head * HID + lc], s1 = attS[head * HID + lc + 1];
        float d0 = attD[head * HID + lc], d1 = attD[head * HID + lc + 1];
        #pragma unroll
        for (int mt = 0; mt < 2; mt++) {
            ps0[mt] += acc[mt][nt][0] * s0 + acc[mt][nt][1] * s1;
            ps1[mt] += acc[mt][nt][2] * s0 + acc[mt][nt][3] * s1;
            pd0[mt] += acc[mt][nt][0] * d0 + acc[mt][nt][1] * d1;
            pd1[mt] += acc[mt][nt][2] * d0 + acc[mt][nt][3] * d1;
        }
    }
    #pragma unroll
    for (int o = 1; o <= 2; o <<= 1) {
        #pragma unroll
        for (int mt = 0; mt < 2; mt++) {
            ps0[mt] += __shfl_xor_sync(0xffffffffu, ps0[mt], o);
            ps1[mt] += __shfl_xor_sync(0xffffffffu, ps1[mt], o);
            pd0[mt] += __shfl_xor_sync(0xffffffffu, pd0[mt], o);
            pd1[mt] += __shfl_xor_sync(0xffffffffu, pd1[mt], o);
        }
    }
    if (tg == 0) {
        #pragma unroll
        for (int mt = 0; mt < 2; mt++) {
            int r = rowBase + wm * 32 + mt * 16 + g;
            if (r < M) {
                g_as[r * HEADS + head] = ps0[mt];
                g_ad[r * HEADS + head] = pd0[mt];
            }
            if (r + 8 < M) {
                g_as[(r + 8) * HEADS + head] = ps1[mt];
                g_ad[(r + 8) * HEADS + head] = pd1[mt];
            }
        }
    }
}

// ---------------- CSR aggregation: warp per dst node, fp16 features ----------------
__device__ __forceinline__ void fma8(float* a, float al, uint4 v) {
    float2 f0 = __half22float2(*(__half2*)&v.x);
    float2 f1 = __half22float2(*(__half2*)&v.y);
    float2 f2 = __half22float2(*(__half2*)&v.z);
    float2 f3 = __half22float2(*(__half2*)&v.w);
    a[0] = fmaf(al, f0.x, a[0]); a[1] = fmaf(al, f0.y, a[1]);
    a[2] = fmaf(al, f1.x, a[2]); a[3] = fmaf(al, f1.y, a[3]);
    a[4] = fmaf(al, f2.x, a[4]); a[5] = fmaf(al, f2.y, a[5]);
    a[6] = fmaf(al, f3.x, a[6]); a[7] = fmaf(al, f3.y, a[7]);
}

__global__ void agg_csr(const __half* __restrict__ hsrc, float* __restrict__ outp,
                        int meanHeads) {
    // fold BN-stats zeroing into this kernel (runs before any bn_stats consumer)
    if (blockIdx.x == 0) {
        g_stats[threadIdx.x] = 0.f;
        g_stats[threadIdx.x + 256] = 0.f;
    }
    int d = (blockIdx.x * blockDim.x + threadIdx.x) >> 5;
    int lane = threadIdx.x & 31;
    if (d >= NN) return;
    int start = g_off[d], end = g_off[d + 1];
    float4 dv = *(const float4*)(g_ad + d * HEADS);
    float d0 = 0.f, d1 = 0.f, d2 = 0.f, d3 = 0.f;
    // pass 1: softmax denominator (no stores)
    for (int e = start + lane; e < end; e += 32) {
        int s = g_csr[e];
        float4 sv = *(const float4*)(g_as + s * HEADS);
        float l0 = sv.x + dv.x; l0 = fmaxf(l0, 0.2f * l0); d0 += __expf(l0);
        float l1 = sv.y + dv.y; l1 = fmaxf(l1, 0.2f * l1); d1 += __expf(l1);
        float l2 = sv.z + dv.z; l2 = fmaxf(l2, 0.2f * l2); d2 += __expf(l2);
        float l3 = sv.w + dv.w; l3 = fmaxf(l3, 0.2f * l3); d3 += __expf(l3);
    }
    #pragma unroll
    for (int o = 16; o > 0; o >>= 1) {
        d0 += __shfl_xor_sync(0xffffffffu, d0, o);
        d1 += __shfl_xor_sync(0xffffffffu, d1, o);
        d2 += __shfl_xor_sync(0xffffffffu, d2, o);
        d3 += __shfl_xor_sync(0xffffffffu, d3, o);
    }
    int hh = lane >> 3;            // lane covers channels [lane*8, lane*8+8)
    float dvh = (hh == 0) ? dv.x : (hh == 1) ? dv.y : (hh == 2) ? dv.z : dv.w;
    float den = (hh == 0) ? d0 : (hh == 1) ? d1 : (hh == 2) ? d2 : d3;
    float invh = 1.f / (den + 1e-16f);
    // pass 2: weighted gather (exp recomputed per lane)
    float a[8] = {0.f, 0.f, 0.f, 0.f, 0.f, 0.f, 0.f, 0.f};
    int e = start;
    for (; e + 2 <= end; e += 2) {
        int s0 = g_csr[e], s1 = g_csr[e + 1];
        float l0 = g_as[s0 * HEADS + hh] + dvh;
        float l1 = g_as[s1 * HEADS + hh] + dvh;
        l0 = fmaxf(l0, 0.2f * l0);
        l1 = fmaxf(l1, 0.2f * l1);
        float w0 = __expf(l0), w1 = __expf(l1);
        uint4 v0 = *((const uint4*)(hsrc + (long)s0 * HC) + lane);
        uint4 v1 = *((const uint4*)(hsrc + (long)s1 * HC) + lane);
        fma8(a, w0, v0);
        fma8(a, w1, v1);
    }
    if (e < end) {
        int s0 = g_csr[e];
        float l0 = g_as[s0 * HEADS + hh] + dvh;
        l0 = fmaxf(l0, 0.2f * l0);
        uint4 v0 = *((const uint4*)(hsrc + (long)s0 * HC) + lane);
        fma8(a, __expf(l0), v0);
    }
    #pragma unroll
    for (int j = 0; j < 8; j++) a[j] *= invh;
    if (!meanHeads) {
        float4* op = (float4*)(outp + (long)d * HC) + lane * 2;
        op[0] = make_float4(a[0], a[1], a[2], a[3]);
        op[1] = make_float4(a[4], a[5], a[6], a[7]);
    } else {
        // mean over heads: lanes L, L^8, L^16, L^24 hold same local channels
        #pragma unroll
        for (int j = 0; j < 8; j++) {
            a[j] += __shfl_xor_sync(0xffffffffu, a[j], 8);
            a[j] += __shfl_xor_sync(0xffffffffu, a[j], 16);
        }
        if (lane < 8) {
            float4* op = (float4*)(outp + (long)d * HID) + lane * 2;
            op[0] = make_float4(0.25f * a[0], 0.25f * a[1], 0.25f * a[2], 0.25f * a[3]);
            op[1] = make_float4(0.25f * a[4], 0.25f * a[5], 0.25f * a[6], 0.25f * a[7]);
        }
    }
}

__global__ void bn_stats(const float* __restrict__ x, int N, int C) {
    int tid = threadIdx.x;
    int c = tid % C;
    int g = tid / C;
    int G = blockDim.x / C;
    int rows_per_block = (N + gridDim.x - 1) / gridDim.x;
    int r0 = blockIdx.x * rows_per_block;
    int r1 = min(N, r0 + rows_per_block);
    float s = 0.f, q = 0.f;
    for (int r = r0 + g; r < r1; r += G) {
        float v = x[(long)r * C + c];
        s += v;
        q += v * v;
    }
    __shared__ float sh[512];
    sh[tid] = s;
    sh[256 + tid] = q;
    __syncthreads();
    if (g == 0) {
        for (int gg = 1; gg < G; gg++) {
            s += sh[gg * C + c];
            q += sh[256 + gg * C + c];
        }
        atomicAdd(&g_stats[c], s);
        atomicAdd(&g_stats[C + c], q);
    }
}

__global__ void bn_finalize(const float* __restrict__ gamma,
                            const float* __restrict__ beta, int N, int C) {
    int c = threadIdx.x;
    if (c >= C) return;
    float invN = 1.f / (float)N;
    float mean = g_stats[c] * invN;
    float var = g_stats[C + c] * invN - mean * mean;
    float sc = gamma[c] * rsqrtf(var + 1e-5f);
    g_scale[c] = sc;
    g_shift[c] = beta[c] - mean * sc;
}

__global__ void bn_apply_elu(float* __restrict__ x, const float* __restrict__ gamma,
                             const float* __restrict__ beta, int N, int C) {
    int i = blockIdx.x * blockDim.x + threadIdx.x;
    if (i >= N * C) return;
    int c = i % C;
    float invN = 1.f / (float)N;
    float mean = g_stats[c] * invN;
    float var = g_stats[C + c] * invN - mean * mean;
    float inv = rsqrtf(var + 1e-5f);
    float v = (x[i] - mean) * inv * gamma[c] + beta[c];
    v = (v > 0.f) ? v : expm1f(v);
    x[i] = v;
}

__global__ void fc_out(const float* __restrict__ W, const float* __restrict__ b,
                       float* __restrict__ out) {
    __shared__ float sW[HID * OUTD];
    for (int l = threadIdx.x; l < HID * OUTD; l += blockDim.x)
        sW[l] = W[l];
    __syncthreads();
    int i = blockIdx.x * blockDim.x + threadIdx.x;
    if (i >= NN * OUTD) return;
    int n = i / OUTD, o = i - n * OUTD;
    const float4* y4 = (const float4*)(g_y + (long)n * HID);
    float acc = b[o];
    #pragma unroll
    for (int k = 0; k < 16; k++) {
        float4 v = y4[k];
        acc += v.x * sW[(4 * k) * OUTD + o];
        acc += v.y * sW[(4 * k + 1) * OUTD + o];
        acc += v.z * sW[(4 * k + 2) * OUTD + o];
        acc += v.w * sW[(4 * k + 3) * OUTD + o];
    }
    out[i] = acc;
}

extern "C" void kernel_launch(void* const* d_in, const int* in_sizes, int n_in,
                              void* d_out, int out_size) {
    const float* x   = (const float*)d_in[0];
    const void*  ei  = d_in[1];
    const float* W1  = (const float*)d_in[2];
    const float* as1 = (const float*)d_in[3];
    const float* ad1 = (const float*)d_in[4];
    const float* W2  = (const float*)d_in[6];
    const float* as2 = (const float*)d_in[7];
    const float* ad2 = (const float*)d_in[8];
    const float* g1  = (const float*)d_in[10];
    const float* be1 = (const float*)d_in[11];
    const float* g2  = (const float*)d_in[12];
    const float* be2 = (const float*)d_in[13];
    const float* pw  = (const float*)d_in[14];
    const float* fcW = (const float*)d_in[15];
    const float* fcb = (const float*)d_in[16];
    float* out = (float*)d_out;

    __half* p_h;
    float *p_agg, *p_y, *p_scale, *p_shift;
    cudaGetSymbolAddress((void**)&p_h, g_h);
    cudaGetSymbolAddress((void**)&p_agg, g_agg);
    cudaGetSymbolAddress((void**)&p_y, g_y);
    cudaGetSymbolAddress((void**)&p_scale, g_scale);
    cudaGetSymbolAddress((void**)&p_shift, g_shift);

    static int smem_set = 0;
    if (!smem_set) {
        cudaFuncSetAttribute(gemm_tf32, cudaFuncAttributeMaxDynamicSharedMemorySize,
                             GEMM_SMEM);
        smem_set = 1;
    }

    dim3 gemmGrid(HC / BNT, (NN + BM - 1) / BM);   // (2, 391)
    int edgeBlocks = (E2 + 255) / 256;
    int aggBlocks  = (NN * 32 + 255) / 256;

    // ---- CSR build ----
    detect_dtype<<<1, 256>>>((const int*)ei);
    convert_idx<<<edgeBlocks, 256>>>(ei);
    hist_deg<<<edgeBlocks, 256>>>();
    scan1<<<NBLK_SCAN, SCAN_BLK>>>();
    scan2<<<1, SCAN_BLK>>>();
    scan3<<<NBLK_SCAN, SCAN_BLK>>>();
    scatter_csr<<<edgeBlocks, 256>>>();

    // ---- layer 1 ----
    gemm_tf32<<<gemmGrid, 256, GEMM_SMEM>>>(x, W1, p_h, as1, ad1, NN,
                                            nullptr, nullptr, nullptr);
    agg_csr<<<aggBlocks, 256>>>(p_h, p_agg, 0);
    bn_stats<<<512, 256>>>(p_agg, NN, HC);
    bn_finalize<<<1, 256>>>(g1, be1, NN, HC);

    // ---- layer 2 (BN1 affine + PReLU fused into A-load; head-mean fused into agg) ----
    gemm_tf32<<<gemmGrid, 256, GEMM_SMEM>>>(p_agg, W2, p_h, as2, ad2, NN,
                                            p_scale, p_shift, pw);
    agg_csr<<<aggBlocks, 256>>>(p_h, p_y, 1);
    bn_stats<<<512, 256>>>(p_y, NN, HID);
    bn_apply_elu<<<(NN * HID + 255) / 256, 256>>>(p_y, g2, be2, NN, HID);
    fc_out<<<(NN * OUTD + 255) / 256, 256>>>(fcW, fcb, out);
}